// round 11
// baseline (speedup 1.0000x reference)
#include <cuda_runtime.h>
#include <math.h>

#define NB 2
#define NK 2
#define NN 4096
#define NT 8
#define NC 3
#define NH 192
#define NS 1638
#define NKN 16
#define NE (NS*NKN)          // 26208
#define NM (NB*NK*NS)        // 6552

typedef unsigned long long u64t;

// ---------------- scratch ----------------
__device__ float g_varpp[NB*NN];
__device__ float g_soft[NB*NN];
__device__ int   g_topidx[NB*NS];
__device__ float g_possel[NB*NS*3];
__device__ float g_masksel[NB*NS];
__device__ float g_x0[NM*10];
__device__ float g_h[NM*NH];
__device__ float g_AB[NM*384];
__device__ float g_t[NM*NH];
__device__ float g_z[NM*NH];
__device__ float g_delta[NM*3];
__device__ int   g_ei[NB*NE];
__device__ float g_ea[NB*NE*4];
__device__ int   g_indeg[NB*NS];
__device__ int   g_revstart[NB*(NS+1)];
__device__ int   g_cursor[NB*NS];
__device__ int   g_revlist[NB*NE];
__device__ float g_Wc0[10*384];          // layer0 combined weight (SIMT path)
__device__ float g_Wcf[9*192*384];       // layers 1..9 combined weights, tf32 fragment layout
__device__ float g_Whf[192*192];         // head_w1, tf32 fragment layout
__device__ float g_W2f[10*192*192];      // w2 (layer0 + layers 1..9), tf32 fragment layout
__device__ float2 g_glut[1024];          // gelu Phi LUT: (base, slope) over [-6,6]

__device__ __forceinline__ float gelu_f(float x){
    return 0.5f*x*(1.0f+erff(x*0.70710678118654752f));
}
__device__ __forceinline__ u64t pk2(float lo, float hi){
    u64t r; asm("mov.b64 %0, {%1, %2};" : "=l"(r) : "f"(lo), "f"(hi)); return r;
}
__device__ __forceinline__ u64t fma2(u64t a, u64t b, u64t c){
    u64t d; asm("fma.rn.f32x2 %0, %1, %2, %3;" : "=l"(d) : "l"(a), "l"(b), "l"(c)); return d;
}
__device__ __forceinline__ float2 upk2(u64t v){
    float2 f; asm("mov.b64 {%0, %1}, %2;" : "=f"(f.x), "=f"(f.y) : "l"(v)); return f;
}
__device__ __forceinline__ unsigned int to_tf32(float v){
    unsigned int t; asm("cvt.rna.tf32.f32 %0, %1;" : "=r"(t) : "f"(v)); return t;
}

// ---------------- stage 0: precompute weights + gelu LUT ----------------
// fragment index for (k,n) in a 192xN matrix: [tn=n>>3][tk8=k>>3][lane=((n&7)<<2)|(k&3)][e=(k>>2)&1]
__global__ void k_prep(const float* __restrict__ c0_w1, const float* __restrict__ cs_w1,
                       const float* __restrict__ head_w1,
                       const float* __restrict__ c0_w2, const float* __restrict__ cs_w2){
    int idx = blockIdx.x*blockDim.x+threadIdx.x;
    const int N0 = 10*384;
    const int NL = 192*384;
    const int NH2 = 192*192;
    if (idx < N0){
        int k = idx/384, n = idx%384;
        float v;
        if (n < NH) v = c0_w1[k*NH+n] - c0_w1[(k+10)*NH+n];
        else        v = c0_w1[(k+10)*NH + (n-NH)];
        g_Wc0[idx]=v;
        return;
    }
    if (idx < N0 + 9*NL){
        int j = idx - N0;
        int li = j / NL;
        int rem = j % NL;
        int k = rem/384, n = rem%384;
        const float* w1 = cs_w1 + (size_t)li*388*NH;
        float v;
        if (n < NH) v = w1[k*NH+n] - w1[(k+NH)*NH+n];
        else        v = w1[(k+NH)*NH + (n-NH)];
        int tn = n>>3, tk8 = k>>3, lanei = ((n&7)<<2)|(k&3), e = (k>>2)&1;
        g_Wcf[(size_t)li*NL + (((size_t)tn*24 + tk8)*32 + lanei)*2 + e] = __uint_as_float(to_tf32(v));
        return;
    }
    if (idx < N0 + 9*NL + NH2){
        int j = idx - N0 - 9*NL;
        int k = j/192, n = j%192;
        float v = head_w1[k*192+n];
        int tn = n>>3, tk8 = k>>3, lanei = ((n&7)<<2)|(k&3), e = (k>>2)&1;
        g_Whf[(((size_t)tn*24 + tk8)*32 + lanei)*2 + e] = __uint_as_float(to_tf32(v));
        return;
    }
    if (idx < N0 + 9*NL + NH2 + 10*NH2){
        int j2 = idx - N0 - 9*NL - NH2;
        int li = j2 / NH2;
        int rem = j2 % NH2;
        int k = rem/192, n = rem%192;
        float v = (li==0) ? c0_w2[k*192+n] : cs_w2[(size_t)(li-1)*NH2 + k*192+n];
        int tn = n>>3, tk8 = k>>3, lanei = ((n&7)<<2)|(k&3), e = (k>>2)&1;
        g_W2f[(size_t)li*NH2 + (((size_t)tn*24 + tk8)*32 + lanei)*2 + e] = __uint_as_float(to_tf32(v));
        return;
    }
    int j3 = idx - (N0 + 9*NL + NH2 + 10*NH2);
    if (j3 < 1024){
        float x0 = -6.0f + 12.0f*j3*(1.0f/1024.0f);
        float x1 = -6.0f + 12.0f*(j3+1)*(1.0f/1024.0f);
        float p0 = 0.5f*(1.0f+erff(x0*0.70710678118654752f));
        float p1 = 0.5f*(1.0f+erff(x1*0.70710678118654752f));
        g_glut[j3] = make_float2(p0, p1-p0);
    }
}

// ---------------- stage 1: per-node temporal variance ----------------
__global__ void k_varpp(const float* __restrict__ vel){
    int idx = blockIdx.x*blockDim.x+threadIdx.x;
    if (idx >= NB*NN) return;
    int b = idx / NN, n = idx % NN;
    float m0=0,m1=0,m2=0;
    #pragma unroll
    for (int t=0;t<NT;t++){
        const float* p = &vel[((b*NT+t)*NN+n)*NC];
        m0 += p[0]; m1 += p[1]; m2 += p[2];
    }
    m0 *= (1.0f/NT); m1 *= (1.0f/NT); m2 *= (1.0f/NT);
    float s=0;
    #pragma unroll
    for (int t=0;t<NT;t++){
        const float* p = &vel[((b*NT+t)*NN+n)*NC];
        float d0=p[0]-m0, d1=p[1]-m1, d2=p[2]-m2;
        s += d0*d0+d1*d1+d2*d2;
    }
    g_varpp[idx] = s*(1.0f/(NT-1));
}

// ---------------- stage 2: batch stats + soft mask ----------------
__global__ __launch_bounds__(1024) void k_stats(const float* __restrict__ am){
    __shared__ float red[1024];
    __shared__ float smean, sstd;
    int b = blockIdx.x, tid = threadIdx.x;
    float s=0;
    for (int n=tid;n<NN;n+=1024) s += g_varpp[b*NN+n];
    red[tid]=s; __syncthreads();
    for (int o=512;o;o>>=1){ if (tid<o) red[tid]+=red[tid+o]; __syncthreads(); }
    if (tid==0) smean = red[0]*(1.0f/NN);
    __syncthreads();
    float mean = smean;
    float s2=0;
    for (int n=tid;n<NN;n+=1024){ float d=g_varpp[b*NN+n]-mean; s2+=d*d; }
    __syncthreads();
    red[tid]=s2; __syncthreads();
    for (int o=512;o;o>>=1){ if (tid<o) red[tid]+=red[tid+o]; __syncthreads(); }
    if (tid==0) sstd = sqrtf(red[0]*(1.0f/(NN-1)));
    __syncthreads();
    float sd = sstd + 1e-8f;
    for (int n=tid;n<NN;n+=1024){
        float zz = (g_varpp[b*NN+n]-mean)/sd;
        float sg = 1.0f/(1.0f+expf(-5.0f*zz));
        g_soft[b*NN+n] = sg*(1.0f-am[b*NN+n]);
    }
}

// ---------------- stage 3: top-S by radix select ----------------
__device__ __forceinline__ unsigned int mapkey_f(float v){
    unsigned int u = __float_as_uint(v);
    return (u & 0x80000000u) ? ~u : (u | 0x80000000u);
}
__global__ __launch_bounds__(1024) void k_select(){
    __shared__ unsigned int hist[256];
    __shared__ unsigned int s2[256];
    __shared__ unsigned int sc[1024];
    __shared__ unsigned int prefix_sh, needed_sh;
    int b = blockIdx.x, tid = threadIdx.x;
    unsigned int prefix = 0;
    unsigned int needed = NS;
    #pragma unroll
    for (int shift=24; shift>=0; shift-=8){
        if (tid < 256) hist[tid]=0;
        __syncthreads();
        unsigned int mask = (shift==24) ? 0u : (0xFFFFFFFFu << (shift+8));
        for (int i=tid;i<NN;i+=1024){
            unsigned int k = mapkey_f(g_varpp[b*NN+i]);
            if ((k & mask) == prefix)
                atomicAdd(&hist[(k>>shift)&0xFFu], 1u);
        }
        __syncthreads();
        if (tid < 256) s2[tid] = hist[tid];
        __syncthreads();
        for (int off=1; off<256; off<<=1){
            unsigned int v = 0;
            if (tid < 256){
                v = s2[tid];
                if (tid+off < 256) v += s2[tid+off];
            }
            __syncthreads();
            if (tid < 256) s2[tid] = v;
            __syncthreads();
        }
        if (tid < 256){
            unsigned int inc = s2[tid];
            unsigned int strict = inc - hist[tid];
            if (strict < needed && inc >= needed){
                prefix_sh = prefix | ((unsigned int)tid << shift);
                needed_sh = needed - strict;
            }
        }
        __syncthreads();
        prefix = prefix_sh; needed = needed_sh;
        __syncthreads();
    }
    unsigned int T = prefix;
    unsigned int total_gt = NS - needed;
    int base = b*NN + tid*4;
    unsigned int k0=mapkey_f(g_varpp[base+0]);
    unsigned int k1=mapkey_f(g_varpp[base+1]);
    unsigned int k2=mapkey_f(g_varpp[base+2]);
    unsigned int k3=mapkey_f(g_varpp[base+3]);
    unsigned int cg = (k0>T)+(k1>T)+(k2>T)+(k3>T);
    unsigned int ce = (k0==T)+(k1==T)+(k2==T)+(k3==T);
    sc[tid]=cg; __syncthreads();
    for (int off=1; off<1024; off<<=1){
        unsigned int v = sc[tid];
        if (tid >= off) v += sc[tid-off];
        __syncthreads(); sc[tid]=v; __syncthreads();
    }
    unsigned int offg = sc[tid]-cg;
    __syncthreads();
    sc[tid]=ce; __syncthreads();
    for (int off=1; off<1024; off<<=1){
        unsigned int v = sc[tid];
        if (tid >= off) v += sc[tid-off];
        __syncthreads(); sc[tid]=v; __syncthreads();
    }
    unsigned int offe = sc[tid]-ce;
    unsigned int keys[4]={k0,k1,k2,k3};
    unsigned int pg=offg, pe=offe;
    #pragma unroll
    for (int q=0;q<4;q++){
        int n = tid*4+q;
        if (keys[q] > T){
            g_topidx[b*NS + pg] = n; pg++;
        } else if (keys[q] == T){
            if (pe < needed) g_topidx[b*NS + total_gt + pe] = n;
            pe++;
        }
    }
}

// ---------------- stage 4: gather ----------------
__global__ void k_gather(const float* __restrict__ u_base, const float* __restrict__ pos,
                         const float* __restrict__ vel){
    int idx = blockIdx.x*blockDim.x+threadIdx.x;
    if (idx >= NB*NS) return;
    int b = idx/NS, s = idx%NS;
    int n = g_topidx[idx];
    float p0=pos[(b*NN+n)*3+0], p1=pos[(b*NN+n)*3+1], p2=pos[(b*NN+n)*3+2];
    g_possel[idx*3+0]=p0; g_possel[idx*3+1]=p1; g_possel[idx*3+2]=p2;
    g_masksel[idx] = g_soft[b*NN+n];
    float vf = g_varpp[b*NN+n];
    float vl0=vel[((b*NT+NT-1)*NN+n)*NC+0];
    float vl1=vel[((b*NT+NT-1)*NN+n)*NC+1];
    float vl2=vel[((b*NT+NT-1)*NN+n)*NC+2];
    for (int k=0;k<NK;k++){
        float* row = &g_x0[((b*NK+k)*NS+s)*10];
        row[0]=u_base[((b*NK+k)*NN+n)*NC+0];
        row[1]=u_base[((b*NK+k)*NN+n)*NC+1];
        row[2]=u_base[((b*NK+k)*NN+n)*NC+2];
        row[3]=vl0; row[4]=vl1; row[5]=vl2;
        row[6]=p0;  row[7]=p1;  row[8]=p2;
        row[9]=vf;
    }
}

// ---------------- stage 5: warp-per-node KNN (+indeg count) ----------------
__global__ __launch_bounds__(128) void k_knn(){
    __shared__ float sd[4][32][16];
    __shared__ int   si[4][32][16];
    int w = threadIdx.x>>5, lane = threadIdx.x&31;
    int node = blockIdx.x*4 + w;
    if (node >= NB*NS) return;
    int b = node/NS, s = node%NS;
    const float* __restrict__ P = &g_possel[b*NS*3];
    float px=P[s*3], py=P[s*3+1], pz=P[s*3+2];
    float bd[16]; int bi[16];
    #pragma unroll
    for (int i=0;i<16;i++){ bd[i]=3.4e38f; bi[i]=0x7fffffff; }
    for (int t=lane; t<NS; t+=32){
        if (t==s) continue;
        float dx=P[t*3]-px, dy=P[t*3+1]-py, dz=P[t*3+2]-pz;
        float d2 = dx*dx+dy*dy+dz*dz;
        if (d2 > bd[15] || (d2==bd[15] && t>bi[15])) continue;
        float cd=d2; int ci=t;
        #pragma unroll
        for (int p=0;p<16;p++){
            bool better = (cd<bd[p]) || (cd==bd[p] && ci<bi[p]);
            if (better){
                float tf=bd[p]; bd[p]=cd; cd=tf;
                int   ti=bi[p]; bi[p]=ci; ci=ti;
            }
        }
    }
    #pragma unroll
    for (int i=0;i<16;i++){ sd[w][lane][i]=bd[i]; si[w][lane][i]=bi[i]; }
    __syncwarp();
    int ptr=0;
    int myres = 0;
    for (int r=0;r<16;r++){
        unsigned long long key =
            ((unsigned long long)__float_as_uint(sd[w][lane][ptr])<<32) |
            (unsigned int)si[w][lane][ptr];
        unsigned long long mn = key;
        #pragma unroll
        for (int o=16;o;o>>=1){
            unsigned long long other = __shfl_xor_sync(0xffffffffu, mn, o);
            if (other < mn) mn = other;
        }
        if (mn == key) ptr++;
        if (lane == r) myres = (int)(unsigned int)(mn & 0xffffffffull);
    }
    if (lane < NKN){
        int i = myres;
        int e = s*NKN + lane;
        g_ei[b*NE+e] = i;
        atomicAdd(&g_indeg[b*NS+i], 1);
        float rx=P[i*3]-px, ry=P[i*3+1]-py, rz=P[i*3+2]-pz;
        float dist = sqrtf(rx*rx+ry*ry+rz*rz);
        float* ea = &g_ea[(b*NE+e)*4];
        ea[0]=rx; ea[1]=ry; ea[2]=rz; ea[3]=dist;
    }
}

// ---------------- stage 6: reverse-CSR ----------------
__global__ void k_zero(){
    int i = blockIdx.x*blockDim.x+threadIdx.x;
    if (i < NB*NS) g_indeg[i]=0;
}
__global__ __launch_bounds__(1024) void k_scan(){
    __shared__ int sc[2048];
    int b = blockIdx.x, tid = threadIdx.x;
    for (int i=tid;i<2048;i+=1024) sc[i] = (i<NS)? g_indeg[b*NS+i] : 0;
    __syncthreads();
    for (int off=1; off<2048; off<<=1){
        int i0=tid, i1=tid+1024;
        int v0 = sc[i0] + (i0>=off ? sc[i0-off] : 0);
        int v1 = sc[i1] + (i1>=off ? sc[i1-off] : 0);
        __syncthreads();
        sc[i0]=v0; sc[i1]=v1;
        __syncthreads();
    }
    for (int s=tid;s<NS;s+=1024){
        int st = s ? sc[s-1] : 0;
        g_revstart[b*(NS+1)+s] = st;
        g_cursor[b*NS+s] = st;
    }
    if (tid==0) g_revstart[b*(NS+1)+NS] = sc[NS-1];
}
__global__ void k_fill(){
    int idx = blockIdx.x*blockDim.x+threadIdx.x;
    if (idx >= NB*NE) return;
    int b = idx/NE, e = idx%NE;
    int i = g_ei[idx];
    int p = atomicAdd(&g_cursor[b*NS+i], 1);
    g_revlist[b*NE+p] = e;
}

// ---------------- tf32 tensor-core GEMM: 64x64 tile, K=192 fixed ----------------
__global__ __launch_bounds__(128) void k_gemmtc(
    const float* __restrict__ X, int Mrows,
    const float* __restrict__ Wf,
    const float* __restrict__ bias, int do_gelu,
    float* __restrict__ Out, int ldo)
{
    __shared__ unsigned int As[64][20];
    int tid = threadIdx.x;
    int lane = tid & 31, wid = tid >> 5;
    int wm = (wid & 1) * 32, wn = (wid >> 1) * 32;
    int bm = blockIdx.y * 64, bn = blockIdx.x * 64;
    float acc[2][4][4] = {};
    int am = tid >> 1, akq = (tid & 1) * 8;
    int grow = bm + am;
    bool rowok = grow < Mrows;
    const float* Xr = X + (size_t)grow * 192;
    const float2* Bf = (const float2*)Wf;
    int tn0 = (bn + wn) >> 3;

    for (int kt = 0; kt < 12; kt++){
        int k0 = kt * 16;
        {
            float4 v0 = {0,0,0,0}, v1 = {0,0,0,0};
            if (rowok){
                v0 = *reinterpret_cast<const float4*>(Xr + k0 + akq);
                v1 = *reinterpret_cast<const float4*>(Xr + k0 + akq + 4);
            }
            As[am][akq+0]=to_tf32(v0.x); As[am][akq+1]=to_tf32(v0.y);
            As[am][akq+2]=to_tf32(v0.z); As[am][akq+3]=to_tf32(v0.w);
            As[am][akq+4]=to_tf32(v1.x); As[am][akq+5]=to_tf32(v1.y);
            As[am][akq+6]=to_tf32(v1.z); As[am][akq+7]=to_tf32(v1.w);
        }
        __syncthreads();
        #pragma unroll
        for (int h=0; h<2; h++){
            int kk = h*8;
            int tk8 = kt*2 + h;
            unsigned int bf0[4], bf1[4];
            #pragma unroll
            for (int nt=0; nt<4; nt++){
                float2 bv = Bf[(((size_t)(tn0+nt))*24 + tk8)*32 + lane];
                bf0[nt] = __float_as_uint(bv.x);
                bf1[nt] = __float_as_uint(bv.y);
            }
            unsigned int af[2][4];
            #pragma unroll
            for (int mt=0; mt<2; mt++){
                int r0 = wm + mt*16 + (lane>>2);
                int c0 = kk + (lane&3);
                af[mt][0] = As[r0][c0];
                af[mt][1] = As[r0+8][c0];
                af[mt][2] = As[r0][c0+4];
                af[mt][3] = As[r0+8][c0+4];
            }
            #pragma unroll
            for (int nt=0; nt<4; nt++){
                #pragma unroll
                for (int mt=0; mt<2; mt++){
                    asm("mma.sync.aligned.m16n8k8.row.col.f32.tf32.tf32.f32 "
                        "{%0,%1,%2,%3}, {%4,%5,%6,%7}, {%8,%9}, {%0,%1,%2,%3};"
                        : "+f"(acc[mt][nt][0]), "+f"(acc[mt][nt][1]),
                          "+f"(acc[mt][nt][2]), "+f"(acc[mt][nt][3])
                        : "r"(af[mt][0]), "r"(af[mt][1]), "r"(af[mt][2]), "r"(af[mt][3]),
                          "r"(bf0[nt]), "r"(bf1[nt]));
                }
            }
        }
        __syncthreads();
    }
    #pragma unroll
    for (int mt=0; mt<2; mt++){
        int r0 = bm + wm + mt*16 + (lane>>2);
        #pragma unroll
        for (int nt=0; nt<4; nt++){
            int c0 = bn + wn + nt*8 + 2*(lane&3);
            float b0v = bias ? bias[c0]   : 0.0f;
            float b1v = bias ? bias[c0+1] : 0.0f;
            if (r0 < Mrows){
                float o0 = acc[mt][nt][0] + b0v;
                float o1 = acc[mt][nt][1] + b1v;
                if (do_gelu){ o0 = gelu_f(o0); o1 = gelu_f(o1); }
                Out[(size_t)r0*ldo + c0]   = o0;
                Out[(size_t)r0*ldo + c0+1] = o1;
            }
            if (r0+8 < Mrows){
                float o2 = acc[mt][nt][2] + b0v;
                float o3 = acc[mt][nt][3] + b1v;
                if (do_gelu){ o2 = gelu_f(o2); o3 = gelu_f(o3); }
                Out[(size_t)(r0+8)*ldo + c0]   = o2;
                Out[(size_t)(r0+8)*ldo + c0+1] = o3;
            }
        }
    }
}

// ---------------- SIMT fp32 GEMM (layer0 only, K=10) ----------------
__global__ __launch_bounds__(128) void k_gemm3(
    const float* __restrict__ X, int lda, int Mrows, int Kd,
    const float* __restrict__ W, int ldw,
    const float* __restrict__ bias, int do_gelu,
    float* __restrict__ Out, int ldo)
{
    __shared__ float As[8][64];
    __shared__ float Bs[8][64];
    int tid = threadIdx.x;
    int tx = tid & 7, ty = tid >> 3;
    int bm = blockIdx.y * 64, bn = blockIdx.x * 64;
    u64t acc2[2][8] = {};
    int lr = tid >> 1;
    int lk = (tid & 1) * 4;
    int kb = tid >> 4, nb = (tid & 15) * 4;
    int ktiles = (Kd+7)>>3;
    for (int kt=0;kt<ktiles;kt++){
        int k0 = kt*8;
        {
            int grow = bm + lr;
            const float* Xr = X + (size_t)grow*lda;
            #pragma unroll
            for (int q=0;q<4;q++){
                int gk = k0+lk+q;
                As[lk+q][lr] = (grow<Mrows && gk<Kd)? Xr[gk] : 0.0f;
            }
        }
        {
            int gk = k0+kb;
            float4 v = {0.f,0.f,0.f,0.f};
            if (gk < Kd) v = *reinterpret_cast<const float4*>(W + (size_t)gk*ldw + bn + nb);
            *reinterpret_cast<float4*>(&Bs[kb][nb]) = v;
        }
        __syncthreads();
        #pragma unroll
        for (int kk=0;kk<8;kk++){
            float4 a = *reinterpret_cast<const float4*>(&As[kk][ty*4]);
            float4 b0 = *reinterpret_cast<const float4*>(&Bs[kk][tx*4]);
            float4 b1 = *reinterpret_cast<const float4*>(&Bs[kk][32+tx*4]);
            u64t ap[2] = { pk2(a.x,a.y), pk2(a.z,a.w) };
            float br[8]={b0.x,b0.y,b0.z,b0.w,b1.x,b1.y,b1.z,b1.w};
            #pragma unroll
            for (int j=0;j<8;j++){
                u64t bb = pk2(br[j],br[j]);
                acc2[0][j] = fma2(ap[0], bb, acc2[0][j]);
                acc2[1][j] = fma2(ap[1], bb, acc2[1][j]);
            }
        }
        __syncthreads();
    }
    #pragma unroll
    for (int i=0;i<2;i++){
        int rbase = bm + ty*4 + i*2;
        #pragma unroll
        for (int j=0;j<8;j++){
            int c = bn + ((j<4)? (tx*4+j) : (32+tx*4+(j-4)));
            float2 v = upk2(acc2[i][j]);
            float bv = bias ? bias[c] : 0.0f;
            if (rbase < Mrows){
                float o = v.x + bv;
                if (do_gelu) o = gelu_f(o);
                Out[(size_t)rbase*ldo + c] = o;
            }
            if (rbase+1 < Mrows){
                float o = v.y + bv;
                if (do_gelu) o = gelu_f(o);
                Out[(size_t)(rbase+1)*ldo + c] = o;
            }
        }
    }
}

// ---------------- FUSED: edge aggregation (LUT gelu) + tf32 GEMM2 + deg*b2 + LN + residual ----------------
// block = 32 node-rows, 256 threads / 8 warps.
// Phase 1: warp w edge-aggregates rows w*4..w*4+3 -> tf32 into As.
// Phase 2: tf32 mma (warp = 16 rows x 48 cols), then LN epilogue.
__global__ __launch_bounds__(256) void k_edgeln(
    const float* __restrict__ w1c, const float* __restrict__ b1,
    const float* __restrict__ W2f,
    const float* __restrict__ b2,
    const float* __restrict__ gamma, const float* __restrict__ beta,
    int add_resid, float* __restrict__ outp)
{
    __shared__ unsigned int As[32*196];   // G tile tf32; reused as fp32 C after mma
    __shared__ float sW[4*NH];
    __shared__ float sb[NH];
    __shared__ float2 sL[1024];
    int tid = threadIdx.x;
    int lane = tid & 31, w = tid >> 5;
    int bm = blockIdx.x*32;
    for (int i=tid;i<4*NH;i+=256) sW[i]=w1c[i];
    for (int i=tid;i<NH;i+=256)   sb[i]=b1[i];
    for (int i=tid;i<1024;i+=256) sL[i]=g_glut[i];
    __syncthreads();

    // ---- phase 1: edge aggregation, 4 rows per warp ----
    #pragma unroll 1
    for (int i=0;i<4;i++){
        int row = w*4+i;
        int r = bm + row;
        if (r < NM){
            int s = r % NS;
            int bk = r / NS;
            int b = bk / NK;
            float a[6], acc[6];
            #pragma unroll
            for (int c=0;c<6;c++){
                a[c] = g_AB[r*384 + lane + 32*c] + sb[lane + 32*c];
                acc[c]=0.0f;
            }
            int st = g_revstart[b*(NS+1)+s];
            int en = g_revstart[b*(NS+1)+s+1];
            for (int t=st;t<en;t++){
                int e = g_revlist[b*NE + t];
                int j = e >> 4;
                const float* __restrict__ eap = &g_ea[(b*NE + e)*4];
                float e0=eap[0], e1=eap[1], e2=eap[2], e3=eap[3];
                const float* __restrict__ bmrow = &g_AB[(bk*NS + j)*384 + NH];
                #pragma unroll
                for (int c=0;c<6;c++){
                    int col = lane + 32*c;
                    float pre = a[c] + bmrow[col]
                              + e0*sW[col] + e1*sW[NH+col] + e2*sW[2*NH+col] + e3*sW[3*NH+col];
                    float u = (pre + 6.0f) * (1024.0f/12.0f);
                    u = fminf(fmaxf(u, 0.0f), 1023.999f);
                    int ii = (int)u;
                    float fr = u - (float)ii;
                    float2 lv = sL[ii];
                    acc[c] = fmaf(pre, fmaf(fr, lv.y, lv.x), acc[c]);
                }
            }
            #pragma unroll
            for (int c=0;c<6;c++) As[row*196 + lane + 32*c] = to_tf32(acc[c]);
        } else {
            #pragma unroll
            for (int c=0;c<6;c++) As[row*196 + lane + 32*c] = 0u;
        }
    }
    __syncthreads();

    // ---- phase 2: tf32 mma, warp = 16 rows x 48 cols ----
    int wm = (w>>2)*16;
    int tn0 = (w&3)*6;
    const float2* Bf = (const float2*)W2f;
    float acc[6][4] = {};
    #pragma unroll 4
    for (int tk8=0; tk8<24; tk8++){
        int c0 = tk8*8 + (lane&3);
        int r0 = wm + (lane>>2);
        unsigned int a0 = As[r0*196 + c0];
        unsigned int a1 = As[(r0+8)*196 + c0];
        unsigned int a2 = As[r0*196 + c0+4];
        unsigned int a3 = As[(r0+8)*196 + c0+4];
        #pragma unroll
        for (int nt=0; nt<6; nt++){
            float2 bv = Bf[(((size_t)(tn0+nt))*24 + tk8)*32 + lane];
            asm("mma.sync.aligned.m16n8k8.row.col.f32.tf32.tf32.f32 "
                "{%0,%1,%2,%3}, {%4,%5,%6,%7}, {%8,%9}, {%0,%1,%2,%3};"
                : "+f"(acc[nt][0]), "+f"(acc[nt][1]), "+f"(acc[nt][2]), "+f"(acc[nt][3])
                : "r"(a0), "r"(a1), "r"(a2), "r"(a3),
                  "r"(__float_as_uint(bv.x)), "r"(__float_as_uint(bv.y)));
        }
    }
    __syncthreads();
    float* Cs = (float*)As;
    {
        int r = wm + (lane>>2);
        #pragma unroll
        for (int nt=0; nt<6; nt++){
            int c = (tn0+nt)*8 + 2*(lane&3);
            Cs[r*196+c]       = acc[nt][0];
            Cs[r*196+c+1]     = acc[nt][1];
            Cs[(r+8)*196+c]   = acc[nt][2];
            Cs[(r+8)*196+c+1] = acc[nt][3];
        }
    }
    __syncthreads();
    // ---- LN epilogue: warp w owns rows w*4..w*4+3 ----
    #pragma unroll
    for (int i=0;i<4;i++){
        int row = w*4+i;
        int r = bm + row;
        if (r >= NM) continue;
        int s = r % NS;
        int b = r / (NK*NS);
        float deg = (float)g_indeg[b*NS+s];
        float xr[6];
        float sum=0;
        #pragma unroll
        for (int c=0;c<6;c++){
            int col = lane + 32*c;
            float v = Cs[row*196 + col] + deg*b2[col];
            xr[c]=v; sum+=v;
        }
        #pragma unroll
        for (int o=16;o;o>>=1) sum += __shfl_xor_sync(0xffffffffu,sum,o);
        float mu = sum*(1.0f/NH);
        float vs=0;
        #pragma unroll
        for (int c=0;c<6;c++){ float d=xr[c]-mu; vs+=d*d; }
        #pragma unroll
        for (int o=16;o;o>>=1) vs += __shfl_xor_sync(0xffffffffu,vs,o);
        float inv = 1.0f/sqrtf(vs*(1.0f/NH)+1e-5f);
        #pragma unroll
        for (int c=0;c<6;c++){
            int col = lane + 32*c;
            float y = (xr[c]-mu)*inv*gamma[col] + beta[col];
            if (add_resid) y += g_h[(size_t)r*NH+col];
            outp[(size_t)r*NH+col] = y;
        }
    }
}

// ---------------- standalone LN (head) ----------------
__global__ __launch_bounds__(256) void k_ln(const float* __restrict__ in,
                     const float* __restrict__ gamma, const float* __restrict__ beta,
                     float* __restrict__ outp){
    int tid = threadIdx.x;
    int warp = (blockIdx.x*blockDim.x + tid) >> 5;
    int lane = tid & 31;
    int r = warp;
    float x[6];
    float sum=0;
    #pragma unroll
    for (int c=0;c<6;c++){
        int col = lane + 32*c;
        float v = in[r*NH+col];
        x[c]=v; sum+=v;
    }
    #pragma unroll
    for (int o=16;o;o>>=1) sum += __shfl_xor_sync(0xffffffffu,sum,o);
    float mu = sum*(1.0f/NH);
    float vs=0;
    #pragma unroll
    for (int c=0;c<6;c++){ float d=x[c]-mu; vs+=d*d; }
    #pragma unroll
    for (int o=16;o;o>>=1) vs += __shfl_xor_sync(0xffffffffu,vs,o);
    float inv = 1.0f/sqrtf(vs*(1.0f/NH)+1e-5f);
    #pragma unroll
    for (int c=0;c<6;c++){
        int col = lane + 32*c;
        outp[r*NH+col] = (x[c]-mu)*inv*gamma[col] + beta[col];
    }
}

// ---------------- head projection H->3 + mask ----------------
__global__ __launch_bounds__(256) void k_headout(const float* __restrict__ w2, const float* __restrict__ b2){
    int tid = threadIdx.x;
    int warp = (blockIdx.x*blockDim.x + tid) >> 5;
    int lane = tid & 31;
    int r = warp;
    int s = r % NS;
    int b = r / (NK*NS);
    float z6[6];
    #pragma unroll
    for (int c=0;c<6;c++) z6[c] = g_z[r*NH + lane + 32*c];
    float d[3];
    #pragma unroll
    for (int cc=0;cc<3;cc++){
        float p=0;
        #pragma unroll
        for (int c=0;c<6;c++){ int col = lane + 32*c; p += z6[c]*w2[col*3+cc]; }
        #pragma unroll
        for (int o=16;o;o>>=1) p += __shfl_xor_sync(0xffffffffu,p,o);
        d[cc]=p;
    }
    if (lane==0){
        float ms = g_masksel[b*NS+s];
        #pragma unroll
        for (int cc=0;cc<3;cc++) g_delta[r*3+cc] = (d[cc]+b2[cc])*ms;
    }
}

// ---------------- output ----------------
__global__ void k_outbase(const float* __restrict__ u, const float* __restrict__ am,
                          float* __restrict__ out){
    int idx = blockIdx.x*blockDim.x+threadIdx.x;
    if (idx >= NB*NK*NN*NC) return;
    int n = (idx/NC) % NN;
    int b = idx / (NC*NN*NK);
    out[idx] = u[idx]*(1.0f-am[b*NN+n]);
}
__global__ void k_scatter(const float* __restrict__ u, const float* __restrict__ am,
                          float* __restrict__ out){
    int idx = blockIdx.x*blockDim.x+threadIdx.x;
    if (idx >= NB*NK*NS*NC) return;
    int c = idx % NC;
    int s = (idx/NC) % NS;
    int k = (idx/(NC*NS)) % NK;
    int b = idx / (NC*NS*NK);
    int n = g_topidx[b*NS+s];
    float f = 1.0f - am[b*NN+n];
    int oi = ((b*NK+k)*NN+n)*NC + c;
    out[oi] = (u[oi] + g_delta[((b*NK+k)*NS+s)*3 + c]) * f;
}

// ---------------- launch ----------------
extern "C" void kernel_launch(void* const* d_in, const int* in_sizes, int n_in,
                              void* d_out, int out_size){
    const float* u_base   = (const float*)d_in[0];
    const float* pos      = (const float*)d_in[1];
    const float* vel      = (const float*)d_in[2];
    const float* am       = (const float*)d_in[3];
    const float* c0_w1    = (const float*)d_in[4];
    const float* c0_b1    = (const float*)d_in[5];
    const float* c0_w2    = (const float*)d_in[6];
    const float* c0_b2    = (const float*)d_in[7];
    const float* c0_g     = (const float*)d_in[8];
    const float* c0_be    = (const float*)d_in[9];
    const float* cs_w1    = (const float*)d_in[10];
    const float* cs_b1    = (const float*)d_in[11];
    const float* cs_w2    = (const float*)d_in[12];
    const float* cs_b2    = (const float*)d_in[13];
    const float* cs_g     = (const float*)d_in[14];
    const float* cs_be    = (const float*)d_in[15];
    const float* head_g   = (const float*)d_in[16];
    const float* head_be  = (const float*)d_in[17];
    const float* head_w1  = (const float*)d_in[18];
    const float* head_b1  = (const float*)d_in[19];
    const float* head_w2  = (const float*)d_in[20];
    const float* head_b2  = (const float*)d_in[21];
    float* out = (float*)d_out;

    float *x0p, *hp, *ABp, *tp, *zp, *wc0p, *wcfp, *whfp, *w2fp;
    cudaGetSymbolAddress((void**)&x0p,  g_x0);
    cudaGetSymbolAddress((void**)&hp,   g_h);
    cudaGetSymbolAddress((void**)&ABp,  g_AB);
    cudaGetSymbolAddress((void**)&tp,   g_t);
    cudaGetSymbolAddress((void**)&zp,   g_z);
    cudaGetSymbolAddress((void**)&wc0p, g_Wc0);
    cudaGetSymbolAddress((void**)&wcfp, g_Wcf);
    cudaGetSymbolAddress((void**)&whfp, g_Whf);
    cudaGetSymbolAddress((void**)&w2fp, g_W2f);

    const int PREP_TOT = 10*384 + 9*192*384 + 192*192 + 10*192*192 + 1024;
    k_prep<<<(PREP_TOT+255)/256,256>>>(c0_w1, cs_w1, head_w1, c0_w2, cs_w2);
    k_varpp<<<(NB*NN+255)/256,256>>>(vel);
    k_stats<<<NB,1024>>>(am);
    k_select<<<NB,1024>>>();
    k_zero<<<(NB*NS+255)/256,256>>>();
    k_gather<<<(NB*NS+255)/256,256>>>(u_base,pos,vel);
    k_knn<<<(NB*NS+3)/4,128>>>();
    k_scan<<<NB,1024>>>();
    k_fill<<<(NB*NE+255)/256,256>>>();

    dim3 grid_ab(6,(NM+63)/64);        // 6 x 103
    dim3 grid_hd(3,(NM+63)/64);
    const int LN_BLOCKS = (NM+31)/32;  // 205
    const int EDGE_BLOCKS = NM/8;      // 819

    for (int l=0;l<10;l++){
        const float *w1raw, *w1c, *b1, *b2, *gm, *bt;
        int resid;
        if (l==0){
            w1raw=c0_w1; w1c=w1raw+2*10*NH; b1=c0_b1;
            b2=c0_b2; gm=c0_g; bt=c0_be; resid=0;
            k_gemm3<<<grid_ab,128>>>(x0p,10,NM,10,wc0p,384,nullptr,0,ABp,384);
        } else {
            int li=l-1;
            w1raw=cs_w1+(size_t)li*388*NH; w1c=w1raw+2*NH*NH; b1=cs_b1+li*NH;
            b2=cs_b2+li*NH;
            gm=cs_g+li*NH; bt=cs_be+li*NH; resid=1;
            k_gemmtc<<<grid_ab,128>>>(hp,NM,wcfp+(size_t)li*192*384,nullptr,0,ABp,384);
        }
        // fused: edge pull + LUT gelu + GEMM2 (tf32) + deg*b2 + LN (+residual)
        k_edgeln<<<LN_BLOCKS,256>>>(w1c, b1, w2fp+(size_t)l*192*192, b2, gm, bt, resid, hp);
    }

    // head
    k_ln<<<EDGE_BLOCKS,256>>>(hp,head_g,head_be,tp);
    k_gemmtc<<<grid_hd,128>>>(tp,NM,whfp,head_b1,1,zp,NH);
    k_headout<<<EDGE_BLOCKS,256>>>(head_w2,head_b2);

    // output
    k_outbase<<<(NB*NK*NN*NC+255)/256,256>>>(u_base,am,out);
    k_scatter<<<(NB*NK*NS*NC+255)/256,256>>>(u_base,am,out);
}

// round 14
// speedup vs baseline: 1.2939x; 1.2939x over previous
#include <cuda_runtime.h>
#include <math.h>

#define NB 2
#define NK 2
#define NN 4096
#define NT 8
#define NC 3
#define NH 192
#define NS 1638
#define NKN 16
#define NE (NS*NKN)          // 26208
#define NM (NB*NK*NS)        // 6552

typedef unsigned long long u64t;

// ---------------- scratch ----------------
__device__ float g_varpp[NB*NN];
__device__ float g_soft[NB*NN];
__device__ int   g_topidx[NB*NS];
__device__ float g_possel[NB*NS*3];
__device__ float g_masksel[NB*NS];
__device__ float g_x0[NM*10];
__device__ float g_h[NM*NH];
__device__ float g_AB[NM*384];
__device__ float g_G[NM*NH];
__device__ float g_t[NM*NH];
__device__ float g_z[NM*NH];
__device__ float g_delta[NM*3];
__device__ int   g_ei[NB*NE];
__device__ float g_ea[NB*NE*4];
__device__ int   g_indeg[NB*NS];
__device__ int   g_revstart[NB*(NS+1)];
__device__ int   g_cursor[NB*NS];
__device__ int   g_revlist[NB*NE];
__device__ float g_Wc0[10*384];          // layer0 combined weight (SIMT path)
__device__ float g_Wcf[9*192*384];       // layers 1..9 combined weights, tf32 fragment layout
__device__ float g_Whf[192*192];         // head_w1, tf32 fragment layout
__device__ float g_W2f[10*192*192];      // w2 (layer0 + layers 1..9), tf32 fragment layout
__device__ float2 g_glut[1024];          // gelu Phi LUT: (base, slope) over [-6,6]

__device__ __forceinline__ float gelu_f(float x){
    return 0.5f*x*(1.0f+erff(x*0.70710678118654752f));
}
__device__ __forceinline__ u64t pk2(float lo, float hi){
    u64t r; asm("mov.b64 %0, {%1, %2};" : "=l"(r) : "f"(lo), "f"(hi)); return r;
}
__device__ __forceinline__ u64t fma2(u64t a, u64t b, u64t c){
    u64t d; asm("fma.rn.f32x2 %0, %1, %2, %3;" : "=l"(d) : "l"(a), "l"(b), "l"(c)); return d;
}
__device__ __forceinline__ float2 upk2(u64t v){
    float2 f; asm("mov.b64 {%0, %1}, %2;" : "=f"(f.x), "=f"(f.y) : "l"(v)); return f;
}
__device__ __forceinline__ unsigned int to_tf32(float v){
    unsigned int t; asm("cvt.rna.tf32.f32 %0, %1;" : "=r"(t) : "f"(v)); return t;
}

// ---------------- stage 0: precompute weights + gelu LUT ----------------
// fragment index for (k,n) in a 192xN matrix: [tn=n>>3][tk8=k>>3][lane=((n&7)<<2)|(k&3)][e=(k>>2)&1]
__global__ void k_prep(const float* __restrict__ c0_w1, const float* __restrict__ cs_w1,
                       const float* __restrict__ head_w1,
                       const float* __restrict__ c0_w2, const float* __restrict__ cs_w2){
    int idx = blockIdx.x*blockDim.x+threadIdx.x;
    const int N0 = 10*384;
    const int NL = 192*384;
    const int NH2 = 192*192;
    if (idx < N0){
        int k = idx/384, n = idx%384;
        float v;
        if (n < NH) v = c0_w1[k*NH+n] - c0_w1[(k+10)*NH+n];
        else        v = c0_w1[(k+10)*NH + (n-NH)];
        g_Wc0[idx]=v;
        return;
    }
    if (idx < N0 + 9*NL){
        int j = idx - N0;
        int li = j / NL;
        int rem = j % NL;
        int k = rem/384, n = rem%384;
        const float* w1 = cs_w1 + (size_t)li*388*NH;
        float v;
        if (n < NH) v = w1[k*NH+n] - w1[(k+NH)*NH+n];
        else        v = w1[(k+NH)*NH + (n-NH)];
        int tn = n>>3, tk8 = k>>3, lanei = ((n&7)<<2)|(k&3), e = (k>>2)&1;
        g_Wcf[(size_t)li*NL + (((size_t)tn*24 + tk8)*32 + lanei)*2 + e] = __uint_as_float(to_tf32(v));
        return;
    }
    if (idx < N0 + 9*NL + NH2){
        int j = idx - N0 - 9*NL;
        int k = j/192, n = j%192;
        float v = head_w1[k*192+n];
        int tn = n>>3, tk8 = k>>3, lanei = ((n&7)<<2)|(k&3), e = (k>>2)&1;
        g_Whf[(((size_t)tn*24 + tk8)*32 + lanei)*2 + e] = __uint_as_float(to_tf32(v));
        return;
    }
    if (idx < N0 + 9*NL + NH2 + 10*NH2){
        int j2 = idx - N0 - 9*NL - NH2;
        int li = j2 / NH2;
        int rem = j2 % NH2;
        int k = rem/192, n = rem%192;
        float v = (li==0) ? c0_w2[k*192+n] : cs_w2[(size_t)(li-1)*NH2 + k*192+n];
        int tn = n>>3, tk8 = k>>3, lanei = ((n&7)<<2)|(k&3), e = (k>>2)&1;
        g_W2f[(size_t)li*NH2 + (((size_t)tn*24 + tk8)*32 + lanei)*2 + e] = __uint_as_float(to_tf32(v));
        return;
    }
    int j3 = idx - (N0 + 9*NL + NH2 + 10*NH2);
    if (j3 < 1024){
        float x0 = -6.0f + 12.0f*j3*(1.0f/1024.0f);
        float x1 = -6.0f + 12.0f*(j3+1)*(1.0f/1024.0f);
        float p0 = 0.5f*(1.0f+erff(x0*0.70710678118654752f));
        float p1 = 0.5f*(1.0f+erff(x1*0.70710678118654752f));
        g_glut[j3] = make_float2(p0, p1-p0);
    }
}

// ---------------- stage 1: per-node temporal variance ----------------
__global__ void k_varpp(const float* __restrict__ vel){
    int idx = blockIdx.x*blockDim.x+threadIdx.x;
    if (idx >= NB*NN) return;
    int b = idx / NN, n = idx % NN;
    float m0=0,m1=0,m2=0;
    #pragma unroll
    for (int t=0;t<NT;t++){
        const float* p = &vel[((b*NT+t)*NN+n)*NC];
        m0 += p[0]; m1 += p[1]; m2 += p[2];
    }
    m0 *= (1.0f/NT); m1 *= (1.0f/NT); m2 *= (1.0f/NT);
    float s=0;
    #pragma unroll
    for (int t=0;t<NT;t++){
        const float* p = &vel[((b*NT+t)*NN+n)*NC];
        float d0=p[0]-m0, d1=p[1]-m1, d2=p[2]-m2;
        s += d0*d0+d1*d1+d2*d2;
    }
    g_varpp[idx] = s*(1.0f/(NT-1));
}

// ---------------- stage 2: batch stats + soft mask ----------------
__global__ __launch_bounds__(1024) void k_stats(const float* __restrict__ am){
    __shared__ float red[1024];
    __shared__ float smean, sstd;
    int b = blockIdx.x, tid = threadIdx.x;
    float s=0;
    for (int n=tid;n<NN;n+=1024) s += g_varpp[b*NN+n];
    red[tid]=s; __syncthreads();
    for (int o=512;o;o>>=1){ if (tid<o) red[tid]+=red[tid+o]; __syncthreads(); }
    if (tid==0) smean = red[0]*(1.0f/NN);
    __syncthreads();
    float mean = smean;
    float s2=0;
    for (int n=tid;n<NN;n+=1024){ float d=g_varpp[b*NN+n]-mean; s2+=d*d; }
    __syncthreads();
    red[tid]=s2; __syncthreads();
    for (int o=512;o;o>>=1){ if (tid<o) red[tid]+=red[tid+o]; __syncthreads(); }
    if (tid==0) sstd = sqrtf(red[0]*(1.0f/(NN-1)));
    __syncthreads();
    float sd = sstd + 1e-8f;
    for (int n=tid;n<NN;n+=1024){
        float zz = (g_varpp[b*NN+n]-mean)/sd;
        float sg = 1.0f/(1.0f+expf(-5.0f*zz));
        g_soft[b*NN+n] = sg*(1.0f-am[b*NN+n]);
    }
}

// ---------------- stage 3: top-S by radix select ----------------
__device__ __forceinline__ unsigned int mapkey_f(float v){
    unsigned int u = __float_as_uint(v);
    return (u & 0x80000000u) ? ~u : (u | 0x80000000u);
}
__global__ __launch_bounds__(1024) void k_select(){
    __shared__ unsigned int hist[256];
    __shared__ unsigned int s2[256];
    __shared__ unsigned int sc[1024];
    __shared__ unsigned int prefix_sh, needed_sh;
    int b = blockIdx.x, tid = threadIdx.x;
    unsigned int prefix = 0;
    unsigned int needed = NS;
    #pragma unroll
    for (int shift=24; shift>=0; shift-=8){
        if (tid < 256) hist[tid]=0;
        __syncthreads();
        unsigned int mask = (shift==24) ? 0u : (0xFFFFFFFFu << (shift+8));
        for (int i=tid;i<NN;i+=1024){
            unsigned int k = mapkey_f(g_varpp[b*NN+i]);
            if ((k & mask) == prefix)
                atomicAdd(&hist[(k>>shift)&0xFFu], 1u);
        }
        __syncthreads();
        if (tid < 256) s2[tid] = hist[tid];
        __syncthreads();
        for (int off=1; off<256; off<<=1){
            unsigned int v = 0;
            if (tid < 256){
                v = s2[tid];
                if (tid+off < 256) v += s2[tid+off];
            }
            __syncthreads();
            if (tid < 256) s2[tid] = v;
            __syncthreads();
        }
        if (tid < 256){
            unsigned int inc = s2[tid];
            unsigned int strict = inc - hist[tid];
            if (strict < needed && inc >= needed){
                prefix_sh = prefix | ((unsigned int)tid << shift);
                needed_sh = needed - strict;
            }
        }
        __syncthreads();
        prefix = prefix_sh; needed = needed_sh;
        __syncthreads();
    }
    unsigned int T = prefix;
    unsigned int total_gt = NS - needed;
    int base = b*NN + tid*4;
    unsigned int k0=mapkey_f(g_varpp[base+0]);
    unsigned int k1=mapkey_f(g_varpp[base+1]);
    unsigned int k2=mapkey_f(g_varpp[base+2]);
    unsigned int k3=mapkey_f(g_varpp[base+3]);
    unsigned int cg = (k0>T)+(k1>T)+(k2>T)+(k3>T);
    unsigned int ce = (k0==T)+(k1==T)+(k2==T)+(k3==T);
    sc[tid]=cg; __syncthreads();
    for (int off=1; off<1024; off<<=1){
        unsigned int v = sc[tid];
        if (tid >= off) v += sc[tid-off];
        __syncthreads(); sc[tid]=v; __syncthreads();
    }
    unsigned int offg = sc[tid]-cg;
    __syncthreads();
    sc[tid]=ce; __syncthreads();
    for (int off=1; off<1024; off<<=1){
        unsigned int v = sc[tid];
        if (tid >= off) v += sc[tid-off];
        __syncthreads(); sc[tid]=v; __syncthreads();
    }
    unsigned int offe = sc[tid]-ce;
    unsigned int keys[4]={k0,k1,k2,k3};
    unsigned int pg=offg, pe=offe;
    #pragma unroll
    for (int q=0;q<4;q++){
        int n = tid*4+q;
        if (keys[q] > T){
            g_topidx[b*NS + pg] = n; pg++;
        } else if (keys[q] == T){
            if (pe < needed) g_topidx[b*NS + total_gt + pe] = n;
            pe++;
        }
    }
}

// ---------------- stage 4: gather ----------------
__global__ void k_gather(const float* __restrict__ u_base, const float* __restrict__ pos,
                         const float* __restrict__ vel){
    int idx = blockIdx.x*blockDim.x+threadIdx.x;
    if (idx >= NB*NS) return;
    int b = idx/NS, s = idx%NS;
    int n = g_topidx[idx];
    float p0=pos[(b*NN+n)*3+0], p1=pos[(b*NN+n)*3+1], p2=pos[(b*NN+n)*3+2];
    g_possel[idx*3+0]=p0; g_possel[idx*3+1]=p1; g_possel[idx*3+2]=p2;
    g_masksel[idx] = g_soft[b*NN+n];
    float vf = g_varpp[b*NN+n];
    float vl0=vel[((b*NT+NT-1)*NN+n)*NC+0];
    float vl1=vel[((b*NT+NT-1)*NN+n)*NC+1];
    float vl2=vel[((b*NT+NT-1)*NN+n)*NC+2];
    for (int k=0;k<NK;k++){
        float* row = &g_x0[((b*NK+k)*NS+s)*10];
        row[0]=u_base[((b*NK+k)*NN+n)*NC+0];
        row[1]=u_base[((b*NK+k)*NN+n)*NC+1];
        row[2]=u_base[((b*NK+k)*NN+n)*NC+2];
        row[3]=vl0; row[4]=vl1; row[5]=vl2;
        row[6]=p0;  row[7]=p1;  row[8]=p2;
        row[9]=vf;
    }
}

// ---------------- stage 5: warp-per-node KNN (+indeg count) ----------------
__global__ __launch_bounds__(128) void k_knn(){
    __shared__ float sd[4][32][16];
    __shared__ int   si[4][32][16];
    int w = threadIdx.x>>5, lane = threadIdx.x&31;
    int node = blockIdx.x*4 + w;
    if (node >= NB*NS) return;
    int b = node/NS, s = node%NS;
    const float* __restrict__ P = &g_possel[b*NS*3];
    float px=P[s*3], py=P[s*3+1], pz=P[s*3+2];
    float bd[16]; int bi[16];
    #pragma unroll
    for (int i=0;i<16;i++){ bd[i]=3.4e38f; bi[i]=0x7fffffff; }
    for (int t=lane; t<NS; t+=32){
        if (t==s) continue;
        float dx=P[t*3]-px, dy=P[t*3+1]-py, dz=P[t*3+2]-pz;
        float d2 = dx*dx+dy*dy+dz*dz;
        if (d2 > bd[15] || (d2==bd[15] && t>bi[15])) continue;
        float cd=d2; int ci=t;
        #pragma unroll
        for (int p=0;p<16;p++){
            bool better = (cd<bd[p]) || (cd==bd[p] && ci<bi[p]);
            if (better){
                float tf=bd[p]; bd[p]=cd; cd=tf;
                int   ti=bi[p]; bi[p]=ci; ci=ti;
            }
        }
    }
    #pragma unroll
    for (int i=0;i<16;i++){ sd[w][lane][i]=bd[i]; si[w][lane][i]=bi[i]; }
    __syncwarp();
    int ptr=0;
    int myres = 0;
    for (int r=0;r<16;r++){
        unsigned long long key =
            ((unsigned long long)__float_as_uint(sd[w][lane][ptr])<<32) |
            (unsigned int)si[w][lane][ptr];
        unsigned long long mn = key;
        #pragma unroll
        for (int o=16;o;o>>=1){
            unsigned long long other = __shfl_xor_sync(0xffffffffu, mn, o);
            if (other < mn) mn = other;
        }
        if (mn == key) ptr++;
        if (lane == r) myres = (int)(unsigned int)(mn & 0xffffffffull);
    }
    if (lane < NKN){
        int i = myres;
        int e = s*NKN + lane;
        g_ei[b*NE+e] = i;
        atomicAdd(&g_indeg[b*NS+i], 1);
        float rx=P[i*3]-px, ry=P[i*3+1]-py, rz=P[i*3+2]-pz;
        float dist = sqrtf(rx*rx+ry*ry+rz*rz);
        float* ea = &g_ea[(b*NE+e)*4];
        ea[0]=rx; ea[1]=ry; ea[2]=rz; ea[3]=dist;
    }
}

// ---------------- stage 6: reverse-CSR ----------------
__global__ void k_zero(){
    int i = blockIdx.x*blockDim.x+threadIdx.x;
    if (i < NB*NS) g_indeg[i]=0;
}
__global__ __launch_bounds__(1024) void k_scan(){
    __shared__ int sc[2048];
    int b = blockIdx.x, tid = threadIdx.x;
    for (int i=tid;i<2048;i+=1024) sc[i] = (i<NS)? g_indeg[b*NS+i] : 0;
    __syncthreads();
    for (int off=1; off<2048; off<<=1){
        int i0=tid, i1=tid+1024;
        int v0 = sc[i0] + (i0>=off ? sc[i0-off] : 0);
        int v1 = sc[i1] + (i1>=off ? sc[i1-off] : 0);
        __syncthreads();
        sc[i0]=v0; sc[i1]=v1;
        __syncthreads();
    }
    for (int s=tid;s<NS;s+=1024){
        int st = s ? sc[s-1] : 0;
        g_revstart[b*(NS+1)+s] = st;
        g_cursor[b*NS+s] = st;
    }
    if (tid==0) g_revstart[b*(NS+1)+NS] = sc[NS-1];
}
__global__ void k_fill(){
    int idx = blockIdx.x*blockDim.x+threadIdx.x;
    if (idx >= NB*NE) return;
    int b = idx/NE, e = idx%NE;
    int i = g_ei[idx];
    int p = atomicAdd(&g_cursor[b*NS+i], 1);
    g_revlist[b*NE+p] = e;
}

// ---------------- tf32 tensor-core GEMM: 64x64 tile, K=192 fixed ----------------
__global__ __launch_bounds__(128) void k_gemmtc(
    const float* __restrict__ X, int Mrows,
    const float* __restrict__ Wf,
    const float* __restrict__ bias, int do_gelu,
    float* __restrict__ Out, int ldo)
{
    __shared__ unsigned int As[64][20];
    int tid = threadIdx.x;
    int lane = tid & 31, wid = tid >> 5;
    int wm = (wid & 1) * 32, wn = (wid >> 1) * 32;
    int bm = blockIdx.y * 64, bn = blockIdx.x * 64;
    float acc[2][4][4] = {};
    int am = tid >> 1, akq = (tid & 1) * 8;
    int grow = bm + am;
    bool rowok = grow < Mrows;
    const float* Xr = X + (size_t)grow * 192;
    const float2* Bf = (const float2*)Wf;
    int tn0 = (bn + wn) >> 3;

    for (int kt = 0; kt < 12; kt++){
        int k0 = kt * 16;
        {
            float4 v0 = {0,0,0,0}, v1 = {0,0,0,0};
            if (rowok){
                v0 = *reinterpret_cast<const float4*>(Xr + k0 + akq);
                v1 = *reinterpret_cast<const float4*>(Xr + k0 + akq + 4);
            }
            As[am][akq+0]=to_tf32(v0.x); As[am][akq+1]=to_tf32(v0.y);
            As[am][akq+2]=to_tf32(v0.z); As[am][akq+3]=to_tf32(v0.w);
            As[am][akq+4]=to_tf32(v1.x); As[am][akq+5]=to_tf32(v1.y);
            As[am][akq+6]=to_tf32(v1.z); As[am][akq+7]=to_tf32(v1.w);
        }
        __syncthreads();
        #pragma unroll
        for (int h=0; h<2; h++){
            int kk = h*8;
            int tk8 = kt*2 + h;
            unsigned int bf0[4], bf1[4];
            #pragma unroll
            for (int nt=0; nt<4; nt++){
                float2 bv = Bf[(((size_t)(tn0+nt))*24 + tk8)*32 + lane];
                bf0[nt] = __float_as_uint(bv.x);
                bf1[nt] = __float_as_uint(bv.y);
            }
            unsigned int af[2][4];
            #pragma unroll
            for (int mt=0; mt<2; mt++){
                int r0 = wm + mt*16 + (lane>>2);
                int c0 = kk + (lane&3);
                af[mt][0] = As[r0][c0];
                af[mt][1] = As[r0+8][c0];
                af[mt][2] = As[r0][c0+4];
                af[mt][3] = As[r0+8][c0+4];
            }
            #pragma unroll
            for (int nt=0; nt<4; nt++){
                #pragma unroll
                for (int mt=0; mt<2; mt++){
                    asm("mma.sync.aligned.m16n8k8.row.col.f32.tf32.tf32.f32 "
                        "{%0,%1,%2,%3}, {%4,%5,%6,%7}, {%8,%9}, {%0,%1,%2,%3};"
                        : "+f"(acc[mt][nt][0]), "+f"(acc[mt][nt][1]),
                          "+f"(acc[mt][nt][2]), "+f"(acc[mt][nt][3])
                        : "r"(af[mt][0]), "r"(af[mt][1]), "r"(af[mt][2]), "r"(af[mt][3]),
                          "r"(bf0[nt]), "r"(bf1[nt]));
                }
            }
        }
        __syncthreads();
    }
    #pragma unroll
    for (int mt=0; mt<2; mt++){
        int r0 = bm + wm + mt*16 + (lane>>2);
        #pragma unroll
        for (int nt=0; nt<4; nt++){
            int c0 = bn + wn + nt*8 + 2*(lane&3);
            float b0v = bias ? bias[c0]   : 0.0f;
            float b1v = bias ? bias[c0+1] : 0.0f;
            if (r0 < Mrows){
                float o0 = acc[mt][nt][0] + b0v;
                float o1 = acc[mt][nt][1] + b1v;
                if (do_gelu){ o0 = gelu_f(o0); o1 = gelu_f(o1); }
                Out[(size_t)r0*ldo + c0]   = o0;
                Out[(size_t)r0*ldo + c0+1] = o1;
            }
            if (r0+8 < Mrows){
                float o2 = acc[mt][nt][2] + b0v;
                float o3 = acc[mt][nt][3] + b1v;
                if (do_gelu){ o2 = gelu_f(o2); o3 = gelu_f(o3); }
                Out[(size_t)(r0+8)*ldo + c0]   = o2;
                Out[(size_t)(r0+8)*ldo + c0+1] = o3;
            }
        }
    }
}

// ---------------- tf32 tensor-core GEMM2 + indeg*b2 + LayerNorm + residual ----------------
__global__ __launch_bounds__(256) void k_gemmlntc(
    const float* __restrict__ X,      // G, NM x 192
    const float* __restrict__ W2f,    // w2 fragment tf32
    const float* __restrict__ b2,
    const float* __restrict__ gamma, const float* __restrict__ beta,
    int add_resid, float* __restrict__ outp)
{
    __shared__ unsigned int As[32*196];
    int tid = threadIdx.x;
    int lane = tid & 31, w = tid >> 5;
    int bm = blockIdx.x*32;
    #pragma unroll
    for (int j=0;j<6;j++){
        int idx4 = tid + j*256;
        int row = idx4/48, c4 = (idx4%48)*4;
        int grow = bm+row;
        float4 v = {0.f,0.f,0.f,0.f};
        if (grow < NM) v = *reinterpret_cast<const float4*>(X + (size_t)grow*192 + c4);
        uint4 t;
        t.x=to_tf32(v.x); t.y=to_tf32(v.y); t.z=to_tf32(v.z); t.w=to_tf32(v.w);
        *reinterpret_cast<uint4*>(&As[row*196 + c4]) = t;
    }
    __syncthreads();
    int wm = (w>>2)*16;
    int tn0 = (w&3)*6;
    const float2* Bf = (const float2*)W2f;
    float acc[6][4] = {};
    #pragma unroll 4
    for (int tk8=0; tk8<24; tk8++){
        int c0 = tk8*8 + (lane&3);
        int r0 = wm + (lane>>2);
        unsigned int a0 = As[r0*196 + c0];
        unsigned int a1 = As[(r0+8)*196 + c0];
        unsigned int a2 = As[r0*196 + c0+4];
        unsigned int a3 = As[(r0+8)*196 + c0+4];
        #pragma unroll
        for (int nt=0; nt<6; nt++){
            float2 bv = Bf[(((size_t)(tn0+nt))*24 + tk8)*32 + lane];
            asm("mma.sync.aligned.m16n8k8.row.col.f32.tf32.tf32.f32 "
                "{%0,%1,%2,%3}, {%4,%5,%6,%7}, {%8,%9}, {%0,%1,%2,%3};"
                : "+f"(acc[nt][0]), "+f"(acc[nt][1]), "+f"(acc[nt][2]), "+f"(acc[nt][3])
                : "r"(a0), "r"(a1), "r"(a2), "r"(a3),
                  "r"(__float_as_uint(bv.x)), "r"(__float_as_uint(bv.y)));
        }
    }
    __syncthreads();
    float* Cs = (float*)As;
    {
        int r = wm + (lane>>2);
        #pragma unroll
        for (int nt=0; nt<6; nt++){
            int c = (tn0+nt)*8 + 2*(lane&3);
            Cs[r*196+c]       = acc[nt][0];
            Cs[r*196+c+1]     = acc[nt][1];
            Cs[(r+8)*196+c]   = acc[nt][2];
            Cs[(r+8)*196+c+1] = acc[nt][3];
        }
    }
    __syncthreads();
    #pragma unroll
    for (int i=0;i<4;i++){
        int row = w*4+i;
        int r = bm + row;
        if (r >= NM) continue;
        int s = r % NS;
        int b = r / (NK*NS);
        float deg = (float)g_indeg[b*NS+s];
        float xr[6];
        float sum=0;
        #pragma unroll
        for (int c=0;c<6;c++){
            int col = lane + 32*c;
            float v = Cs[row*196 + col] + deg*b2[col];
            xr[c]=v; sum+=v;
        }
        #pragma unroll
        for (int o=16;o;o>>=1) sum += __shfl_xor_sync(0xffffffffu,sum,o);
        float mu = sum*(1.0f/NH);
        float vs=0;
        #pragma unroll
        for (int c=0;c<6;c++){ float d=xr[c]-mu; vs+=d*d; }
        #pragma unroll
        for (int o=16;o;o>>=1) vs += __shfl_xor_sync(0xffffffffu,vs,o);
        float inv = 1.0f/sqrtf(vs*(1.0f/NH)+1e-5f);
        #pragma unroll
        for (int c=0;c<6;c++){
            int col = lane + 32*c;
            float y = (xr[c]-mu)*inv*gamma[col] + beta[col];
            if (add_resid) y += g_h[(size_t)r*NH+col];
            outp[(size_t)r*NH+col] = y;
        }
    }
}

// ---------------- SIMT fp32 GEMM (layer0 only, K=10) ----------------
__global__ __launch_bounds__(128) void k_gemm3(
    const float* __restrict__ X, int lda, int Mrows, int Kd,
    const float* __restrict__ W, int ldw,
    const float* __restrict__ bias, int do_gelu,
    float* __restrict__ Out, int ldo)
{
    __shared__ float As[8][64];
    __shared__ float Bs[8][64];
    int tid = threadIdx.x;
    int tx = tid & 7, ty = tid >> 3;
    int bm = blockIdx.y * 64, bn = blockIdx.x * 64;
    u64t acc2[2][8] = {};
    int lr = tid >> 1;
    int lk = (tid & 1) * 4;
    int kb = tid >> 4, nb = (tid & 15) * 4;
    int ktiles = (Kd+7)>>3;
    for (int kt=0;kt<ktiles;kt++){
        int k0 = kt*8;
        {
            int grow = bm + lr;
            const float* Xr = X + (size_t)grow*lda;
            #pragma unroll
            for (int q=0;q<4;q++){
                int gk = k0+lk+q;
                As[lk+q][lr] = (grow<Mrows && gk<Kd)? Xr[gk] : 0.0f;
            }
        }
        {
            int gk = k0+kb;
            float4 v = {0.f,0.f,0.f,0.f};
            if (gk < Kd) v = *reinterpret_cast<const float4*>(W + (size_t)gk*ldw + bn + nb);
            *reinterpret_cast<float4*>(&Bs[kb][nb]) = v;
        }
        __syncthreads();
        #pragma unroll
        for (int kk=0;kk<8;kk++){
            float4 a = *reinterpret_cast<const float4*>(&As[kk][ty*4]);
            float4 b0 = *reinterpret_cast<const float4*>(&Bs[kk][tx*4]);
            float4 b1 = *reinterpret_cast<const float4*>(&Bs[kk][32+tx*4]);
            u64t ap[2] = { pk2(a.x,a.y), pk2(a.z,a.w) };
            float br[8]={b0.x,b0.y,b0.z,b0.w,b1.x,b1.y,b1.z,b1.w};
            #pragma unroll
            for (int j=0;j<8;j++){
                u64t bb = pk2(br[j],br[j]);
                acc2[0][j] = fma2(ap[0], bb, acc2[0][j]);
                acc2[1][j] = fma2(ap[1], bb, acc2[1][j]);
            }
        }
        __syncthreads();
    }
    #pragma unroll
    for (int i=0;i<2;i++){
        int rbase = bm + ty*4 + i*2;
        #pragma unroll
        for (int j=0;j<8;j++){
            int c = bn + ((j<4)? (tx*4+j) : (32+tx*4+(j-4)));
            float2 v = upk2(acc2[i][j]);
            float bv = bias ? bias[c] : 0.0f;
            if (rbase < Mrows){
                float o = v.x + bv;
                if (do_gelu) o = gelu_f(o);
                Out[(size_t)rbase*ldo + c] = o;
            }
            if (rbase+1 < Mrows){
                float o = v.y + bv;
                if (do_gelu) o = gelu_f(o);
                Out[(size_t)(rbase+1)*ldo + c] = o;
            }
        }
    }
}

// ---------------- per-layer edge kernel (LUT gelu, float4 + prefetch) ----------------
__global__ __launch_bounds__(256) void k_edge(const float* __restrict__ w1c, const float* __restrict__ b1){
    __shared__ float sW[4*NH];
    __shared__ float sb[NH];
    __shared__ float2 sL[1024];
    int tid = threadIdx.x;
    for (int i=tid;i<4*NH;i+=blockDim.x) sW[i]=w1c[i];
    for (int i=tid;i<NH;i+=blockDim.x)   sb[i]=b1[i];
    for (int i=tid;i<1024;i+=blockDim.x) sL[i]=g_glut[i];
    __syncthreads();
    int warp = (blockIdx.x*blockDim.x + tid) >> 5;
    int lane = tid & 31;
    int r = warp;
    int s = r % NS;
    int bk = r / NS;
    int b = bk / NK;
    float a[6], acc[6];
    #pragma unroll
    for (int c=0;c<6;c++){
        a[c] = g_AB[r*384 + lane + 32*c] + sb[lane + 32*c];
        acc[c]=0.0f;
    }
    int st = g_revstart[b*(NS+1)+s];
    int en = g_revstart[b*(NS+1)+s+1];
    int e = (st<en) ? g_revlist[b*NE + st] : 0;
    for (int t=st;t<en;t++){
        int e_nxt = (t+1<en) ? g_revlist[b*NE + t + 1] : 0;
        int j = e >> 4;
        float4 ea4 = *reinterpret_cast<const float4*>(&g_ea[(b*NE + e)*4]);
        const float* __restrict__ bmrow = &g_AB[(bk*NS + j)*384 + NH];
        #pragma unroll
        for (int c=0;c<6;c++){
            int col = lane + 32*c;
            float pre = a[c] + bmrow[col]
                      + ea4.x*sW[col] + ea4.y*sW[NH+col] + ea4.z*sW[2*NH+col] + ea4.w*sW[3*NH+col];
            float u = (pre + 6.0f) * (1024.0f/12.0f);
            u = fminf(fmaxf(u, 0.0f), 1023.999f);
            int ii = (int)u;
            float fr = u - (float)ii;
            float2 lv = sL[ii];
            acc[c] = fmaf(pre, fmaf(fr, lv.y, lv.x), acc[c]);
        }
        e = e_nxt;
    }
    #pragma unroll
    for (int c=0;c<6;c++) g_G[r*NH + lane + 32*c] = acc[c];
}

// ---------------- standalone LN (head) ----------------
__global__ __launch_bounds__(256) void k_ln(const float* __restrict__ in,
                     const float* __restrict__ gamma, const float* __restrict__ beta,
                     float* __restrict__ outp){
    int tid = threadIdx.x;
    int warp = (blockIdx.x*blockDim.x + tid) >> 5;
    int lane = tid & 31;
    int r = warp;
    float x[6];
    float sum=0;
    #pragma unroll
    for (int c=0;c<6;c++){
        int col = lane + 32*c;
        float v = in[r*NH+col];
        x[c]=v; sum+=v;
    }
    #pragma unroll
    for (int o=16;o;o>>=1) sum += __shfl_xor_sync(0xffffffffu,sum,o);
    float mu = sum*(1.0f/NH);
    float vs=0;
    #pragma unroll
    for (int c=0;c<6;c++){ float d=x[c]-mu; vs+=d*d; }
    #pragma unroll
    for (int o=16;o;o>>=1) vs += __shfl_xor_sync(0xffffffffu,vs,o);
    float inv = 1.0f/sqrtf(vs*(1.0f/NH)+1e-5f);
    #pragma unroll
    for (int c=0;c<6;c++){
        int col = lane + 32*c;
        outp[r*NH+col] = (x[c]-mu)*inv*gamma[col] + beta[col];
    }
}

// ---------------- head projection H->3 + mask ----------------
__global__ __launch_bounds__(256) void k_headout(const float* __restrict__ w2, const float* __restrict__ b2){
    int tid = threadIdx.x;
    int warp = (blockIdx.x*blockDim.x + tid) >> 5;
    int lane = tid & 31;
    int r = warp;
    int s = r % NS;
    int b = r / (NK*NS);
    float z6[6];
    #pragma unroll
    for (int c=0;c<6;c++) z6[c] = g_z[r*NH + lane + 32*c];
    float d[3];
    #pragma unroll
    for (int cc=0;cc<3;cc++){
        float p=0;
        #pragma unroll
        for (int c=0;c<6;c++){ int col = lane + 32*c; p += z6[c]*w2[col*3+cc]; }
        #pragma unroll
        for (int o=16;o;o>>=1) p += __shfl_xor_sync(0xffffffffu,p,o);
        d[cc]=p;
    }
    if (lane==0){
        float ms = g_masksel[b*NS+s];
        #pragma unroll
        for (int cc=0;cc<3;cc++) g_delta[r*3+cc] = (d[cc]+b2[cc])*ms;
    }
}

// ---------------- output ----------------
__global__ void k_outbase(const float* __restrict__ u, const float* __restrict__ am,
                          float* __restrict__ out){
    int idx = blockIdx.x*blockDim.x+threadIdx.x;
    if (idx >= NB*NK*NN*NC) return;
    int n = (idx/NC) % NN;
    int b = idx / (NC*NN*NK);
    out[idx] = u[idx]*(1.0f-am[b*NN+n]);
}
__global__ void k_scatter(const float* __restrict__ u, const float* __restrict__ am,
                          float* __restrict__ out){
    int idx = blockIdx.x*blockDim.x+threadIdx.x;
    if (idx >= NB*NK*NS*NC) return;
    int c = idx % NC;
    int s = (idx/NC) % NS;
    int k = (idx/(NC*NS)) % NK;
    int b = idx / (NC*NS*NK);
    int n = g_topidx[b*NS+s];
    float f = 1.0f - am[b*NN+n];
    int oi = ((b*NK+k)*NN+n)*NC + c;
    out[oi] = (u[oi] + g_delta[((b*NK+k)*NS+s)*3 + c]) * f;
}

// ---------------- launch ----------------
extern "C" void kernel_launch(void* const* d_in, const int* in_sizes, int n_in,
                              void* d_out, int out_size){
    const float* u_base   = (const float*)d_in[0];
    const float* pos      = (const float*)d_in[1];
    const float* vel      = (const float*)d_in[2];
    const float* am       = (const float*)d_in[3];
    const float* c0_w1    = (const float*)d_in[4];
    const float* c0_b1    = (const float*)d_in[5];
    const float* c0_w2    = (const float*)d_in[6];
    const float* c0_b2    = (const float*)d_in[7];
    const float* c0_g     = (const float*)d_in[8];
    const float* c0_be    = (const float*)d_in[9];
    const float* cs_w1    = (const float*)d_in[10];
    const float* cs_b1    = (const float*)d_in[11];
    const float* cs_w2    = (const float*)d_in[12];
    const float* cs_b2    = (const float*)d_in[13];
    const float* cs_g     = (const float*)d_in[14];
    const float* cs_be    = (const float*)d_in[15];
    const float* head_g   = (const float*)d_in[16];
    const float* head_be  = (const float*)d_in[17];
    const float* head_w1  = (const float*)d_in[18];
    const float* head_b1  = (const float*)d_in[19];
    const float* head_w2  = (const float*)d_in[20];
    const float* head_b2  = (const float*)d_in[21];
    float* out = (float*)d_out;

    float *x0p, *hp, *ABp, *Gp, *tp, *zp, *wc0p, *wcfp, *whfp, *w2fp;
    cudaGetSymbolAddress((void**)&x0p,  g_x0);
    cudaGetSymbolAddress((void**)&hp,   g_h);
    cudaGetSymbolAddress((void**)&ABp,  g_AB);
    cudaGetSymbolAddress((void**)&Gp,   g_G);
    cudaGetSymbolAddress((void**)&tp,   g_t);
    cudaGetSymbolAddress((void**)&zp,   g_z);
    cudaGetSymbolAddress((void**)&wc0p, g_Wc0);
    cudaGetSymbolAddress((void**)&wcfp, g_Wcf);
    cudaGetSymbolAddress((void**)&whfp, g_Whf);
    cudaGetSymbolAddress((void**)&w2fp, g_W2f);

    const int PREP_TOT = 10*384 + 9*192*384 + 192*192 + 10*192*192 + 1024;
    k_prep<<<(PREP_TOT+255)/256,256>>>(c0_w1, cs_w1, head_w1, c0_w2, cs_w2);
    k_varpp<<<(NB*NN+255)/256,256>>>(vel);
    k_stats<<<NB,1024>>>(am);
    k_select<<<NB,1024>>>();
    k_zero<<<(NB*NS+255)/256,256>>>();
    k_gather<<<(NB*NS+255)/256,256>>>(u_base,pos,vel);
    k_knn<<<(NB*NS+3)/4,128>>>();
    k_scan<<<NB,1024>>>();
    k_fill<<<(NB*NE+255)/256,256>>>();

    dim3 grid_ab(6,(NM+63)/64);        // 6 x 103
    dim3 grid_hd(3,(NM+63)/64);
    const int LN_BLOCKS = (NM+31)/32;  // 205
    const int EDGE_BLOCKS = NM/8;      // 819

    for (int l=0;l<10;l++){
        const float *w1raw, *w1c, *b1, *b2, *gm, *bt;
        int resid;
        if (l==0){
            w1raw=c0_w1; w1c=w1raw+2*10*NH; b1=c0_b1;
            b2=c0_b2; gm=c0_g; bt=c0_be; resid=0;
            k_gemm3<<<grid_ab,128>>>(x0p,10,NM,10,wc0p,384,nullptr,0,ABp,384);
        } else {
            int li=l-1;
            w1raw=cs_w1+(size_t)li*388*NH; w1c=w1raw+2*NH*NH; b1=cs_b1+li*NH;
            b2=cs_b2+li*NH;
            gm=cs_g+li*NH; bt=cs_be+li*NH; resid=1;
            k_gemmtc<<<grid_ab,128>>>(hp,NM,wcfp+(size_t)li*192*384,nullptr,0,ABp,384);
        }
        // pull edges, gelu (LUT), sum
        k_edge<<<EDGE_BLOCKS,256>>>(w1c,b1);
        // h = LN(G @ w2 + deg*b2) (+ residual) — tf32 tensor cores
        k_gemmlntc<<<LN_BLOCKS,256>>>(Gp, w2fp+(size_t)l*192*192, b2, gm, bt, resid, hp);
    }

    // head
    k_ln<<<EDGE_BLOCKS,256>>>(hp,head_g,head_be,tp);
    k_gemmtc<<<grid_hd,128>>>(tp,NM,whfp,head_b1,1,zp,NH);
    k_headout<<<EDGE_BLOCKS,256>>>(head_w2,head_b2);

    // output
    k_outbase<<<(NB*NK*NN*NC+255)/256,256>>>(u_base,am,out);
    k_scatter<<<(NB*NK*NS*NC+255)/256,256>>>(u_base,am,out);
}

// round 16
// speedup vs baseline: 1.3227x; 1.0222x over previous
#include <cuda_runtime.h>
#include <math.h>

#define NB 2
#define NK 2
#define NN 4096
#define NT 8
#define NC 3
#define NH 192
#define NS 1638
#define NKN 16
#define NE (NS*NKN)          // 26208
#define NM (NB*NK*NS)        // 6552

typedef unsigned long long u64t;

// ---------------- scratch ----------------
__device__ float g_varpp[NB*NN];
__device__ float g_soft[NB*NN];
__device__ int   g_topidx[NB*NS];
__device__ float g_possel[NB*NS*3];
__device__ float g_masksel[NB*NS];
__device__ float g_x0[NM*10];
__device__ float g_h[NM*NH];
__device__ float g_AB[NM*384];
__device__ float g_G[NM*NH];
__device__ float g_t[NM*NH];
__device__ float g_z[NM*NH];
__device__ float g_delta[NM*3];
__device__ int   g_ei[NB*NE];
__device__ float g_ea[NB*NE*4];
__device__ int   g_indeg[NB*NS];
__device__ int   g_revstart[NB*(NS+1)];
__device__ int   g_cursor[NB*NS];
__device__ int   g_revlist[NB*NE];
__device__ float g_Wc0[10*384];          // layer0 combined weight (SIMT path)
__device__ float g_Wcf[9*192*384];       // layers 1..9 combined weights, tf32 fragment layout
__device__ float g_Whf[192*192];         // head_w1, tf32 fragment layout
__device__ float g_W2f[10*192*192];      // w2 (layer0 + layers 1..9), tf32 fragment layout
__device__ float2 g_glut[1024];          // gelu Phi LUT: (base, slope) over [-6,6]

__device__ __forceinline__ float gelu_f(float x){
    return 0.5f*x*(1.0f+erff(x*0.70710678118654752f));
}
__device__ __forceinline__ u64t pk2(float lo, float hi){
    u64t r; asm("mov.b64 %0, {%1, %2};" : "=l"(r) : "f"(lo), "f"(hi)); return r;
}
__device__ __forceinline__ u64t fma2(u64t a, u64t b, u64t c){
    u64t d; asm("fma.rn.f32x2 %0, %1, %2, %3;" : "=l"(d) : "l"(a), "l"(b), "l"(c)); return d;
}
__device__ __forceinline__ float2 upk2(u64t v){
    float2 f; asm("mov.b64 {%0, %1}, %2;" : "=f"(f.x), "=f"(f.y) : "l"(v)); return f;
}
__device__ __forceinline__ unsigned int to_tf32(float v){
    unsigned int t; asm("cvt.rna.tf32.f32 %0, %1;" : "=r"(t) : "f"(v)); return t;
}

// ---------------- stage 0: precompute weights + gelu LUT ----------------
// fragment index for (k,n) in a 192xN matrix: [tn=n>>3][tk8=k>>3][lane=((n&7)<<2)|(k&3)][e=(k>>2)&1]
__global__ void k_prep(const float* __restrict__ c0_w1, const float* __restrict__ cs_w1,
                       const float* __restrict__ head_w1,
                       const float* __restrict__ c0_w2, const float* __restrict__ cs_w2){
    int idx = blockIdx.x*blockDim.x+threadIdx.x;
    const int N0 = 10*384;
    const int NL = 192*384;
    const int NH2 = 192*192;
    if (idx < N0){
        int k = idx/384, n = idx%384;
        float v;
        if (n < NH) v = c0_w1[k*NH+n] - c0_w1[(k+10)*NH+n];
        else        v = c0_w1[(k+10)*NH + (n-NH)];
        g_Wc0[idx]=v;
        return;
    }
    if (idx < N0 + 9*NL){
        int j = idx - N0;
        int li = j / NL;
        int rem = j % NL;
        int k = rem/384, n = rem%384;
        const float* w1 = cs_w1 + (size_t)li*388*NH;
        float v;
        if (n < NH) v = w1[k*NH+n] - w1[(k+NH)*NH+n];
        else        v = w1[(k+NH)*NH + (n-NH)];
        int tn = n>>3, tk8 = k>>3, lanei = ((n&7)<<2)|(k&3), e = (k>>2)&1;
        g_Wcf[(size_t)li*NL + (((size_t)tn*24 + tk8)*32 + lanei)*2 + e] = __uint_as_float(to_tf32(v));
        return;
    }
    if (idx < N0 + 9*NL + NH2){
        int j = idx - N0 - 9*NL;
        int k = j/192, n = j%192;
        float v = head_w1[k*192+n];
        int tn = n>>3, tk8 = k>>3, lanei = ((n&7)<<2)|(k&3), e = (k>>2)&1;
        g_Whf[(((size_t)tn*24 + tk8)*32 + lanei)*2 + e] = __uint_as_float(to_tf32(v));
        return;
    }
    if (idx < N0 + 9*NL + NH2 + 10*NH2){
        int j2 = idx - N0 - 9*NL - NH2;
        int li = j2 / NH2;
        int rem = j2 % NH2;
        int k = rem/192, n = rem%192;
        float v = (li==0) ? c0_w2[k*192+n] : cs_w2[(size_t)(li-1)*NH2 + k*192+n];
        int tn = n>>3, tk8 = k>>3, lanei = ((n&7)<<2)|(k&3), e = (k>>2)&1;
        g_W2f[(size_t)li*NH2 + (((size_t)tn*24 + tk8)*32 + lanei)*2 + e] = __uint_as_float(to_tf32(v));
        return;
    }
    int j3 = idx - (N0 + 9*NL + NH2 + 10*NH2);
    if (j3 < 1024){
        float x0 = -6.0f + 12.0f*j3*(1.0f/1024.0f);
        float x1 = -6.0f + 12.0f*(j3+1)*(1.0f/1024.0f);
        float p0 = 0.5f*(1.0f+erff(x0*0.70710678118654752f));
        float p1 = 0.5f*(1.0f+erff(x1*0.70710678118654752f));
        g_glut[j3] = make_float2(p0, p1-p0);
    }
}

// ---------------- stage 1: per-node temporal variance ----------------
__global__ void k_varpp(const float* __restrict__ vel){
    int idx = blockIdx.x*blockDim.x+threadIdx.x;
    if (idx >= NB*NN) return;
    int b = idx / NN, n = idx % NN;
    float m0=0,m1=0,m2=0;
    #pragma unroll
    for (int t=0;t<NT;t++){
        const float* p = &vel[((b*NT+t)*NN+n)*NC];
        m0 += p[0]; m1 += p[1]; m2 += p[2];
    }
    m0 *= (1.0f/NT); m1 *= (1.0f/NT); m2 *= (1.0f/NT);
    float s=0;
    #pragma unroll
    for (int t=0;t<NT;t++){
        const float* p = &vel[((b*NT+t)*NN+n)*NC];
        float d0=p[0]-m0, d1=p[1]-m1, d2=p[2]-m2;
        s += d0*d0+d1*d1+d2*d2;
    }
    g_varpp[idx] = s*(1.0f/(NT-1));
}

// ---------------- stage 2: batch stats + soft mask ----------------
__global__ __launch_bounds__(1024) void k_stats(const float* __restrict__ am){
    __shared__ float red[1024];
    __shared__ float smean, sstd;
    int b = blockIdx.x, tid = threadIdx.x;
    float s=0;
    for (int n=tid;n<NN;n+=1024) s += g_varpp[b*NN+n];
    red[tid]=s; __syncthreads();
    for (int o=512;o;o>>=1){ if (tid<o) red[tid]+=red[tid+o]; __syncthreads(); }
    if (tid==0) smean = red[0]*(1.0f/NN);
    __syncthreads();
    float mean = smean;
    float s2=0;
    for (int n=tid;n<NN;n+=1024){ float d=g_varpp[b*NN+n]-mean; s2+=d*d; }
    __syncthreads();
    red[tid]=s2; __syncthreads();
    for (int o=512;o;o>>=1){ if (tid<o) red[tid]+=red[tid+o]; __syncthreads(); }
    if (tid==0) sstd = sqrtf(red[0]*(1.0f/(NN-1)));
    __syncthreads();
    float sd = sstd + 1e-8f;
    for (int n=tid;n<NN;n+=1024){
        float zz = (g_varpp[b*NN+n]-mean)/sd;
        float sg = 1.0f/(1.0f+expf(-5.0f*zz));
        g_soft[b*NN+n] = sg*(1.0f-am[b*NN+n]);
    }
}

// ---------------- stage 3: top-S by radix select ----------------
__device__ __forceinline__ unsigned int mapkey_f(float v){
    unsigned int u = __float_as_uint(v);
    return (u & 0x80000000u) ? ~u : (u | 0x80000000u);
}
__global__ __launch_bounds__(1024) void k_select(){
    __shared__ unsigned int hist[256];
    __shared__ unsigned int s2[256];
    __shared__ unsigned int sc[1024];
    __shared__ unsigned int prefix_sh, needed_sh;
    int b = blockIdx.x, tid = threadIdx.x;
    unsigned int prefix = 0;
    unsigned int needed = NS;
    #pragma unroll
    for (int shift=24; shift>=0; shift-=8){
        if (tid < 256) hist[tid]=0;
        __syncthreads();
        unsigned int mask = (shift==24) ? 0u : (0xFFFFFFFFu << (shift+8));
        for (int i=tid;i<NN;i+=1024){
            unsigned int k = mapkey_f(g_varpp[b*NN+i]);
            if ((k & mask) == prefix)
                atomicAdd(&hist[(k>>shift)&0xFFu], 1u);
        }
        __syncthreads();
        if (tid < 256) s2[tid] = hist[tid];
        __syncthreads();
        for (int off=1; off<256; off<<=1){
            unsigned int v = 0;
            if (tid < 256){
                v = s2[tid];
                if (tid+off < 256) v += s2[tid+off];
            }
            __syncthreads();
            if (tid < 256) s2[tid] = v;
            __syncthreads();
        }
        if (tid < 256){
            unsigned int inc = s2[tid];
            unsigned int strict = inc - hist[tid];
            if (strict < needed && inc >= needed){
                prefix_sh = prefix | ((unsigned int)tid << shift);
                needed_sh = needed - strict;
            }
        }
        __syncthreads();
        prefix = prefix_sh; needed = needed_sh;
        __syncthreads();
    }
    unsigned int T = prefix;
    unsigned int total_gt = NS - needed;
    int base = b*NN + tid*4;
    unsigned int k0=mapkey_f(g_varpp[base+0]);
    unsigned int k1=mapkey_f(g_varpp[base+1]);
    unsigned int k2=mapkey_f(g_varpp[base+2]);
    unsigned int k3=mapkey_f(g_varpp[base+3]);
    unsigned int cg = (k0>T)+(k1>T)+(k2>T)+(k3>T);
    unsigned int ce = (k0==T)+(k1==T)+(k2==T)+(k3==T);
    sc[tid]=cg; __syncthreads();
    for (int off=1; off<1024; off<<=1){
        unsigned int v = sc[tid];
        if (tid >= off) v += sc[tid-off];
        __syncthreads(); sc[tid]=v; __syncthreads();
    }
    unsigned int offg = sc[tid]-cg;
    __syncthreads();
    sc[tid]=ce; __syncthreads();
    for (int off=1; off<1024; off<<=1){
        unsigned int v = sc[tid];
        if (tid >= off) v += sc[tid-off];
        __syncthreads(); sc[tid]=v; __syncthreads();
    }
    unsigned int offe = sc[tid]-ce;
    unsigned int keys[4]={k0,k1,k2,k3};
    unsigned int pg=offg, pe=offe;
    #pragma unroll
    for (int q=0;q<4;q++){
        int n = tid*4+q;
        if (keys[q] > T){
            g_topidx[b*NS + pg] = n; pg++;
        } else if (keys[q] == T){
            if (pe < needed) g_topidx[b*NS + total_gt + pe] = n;
            pe++;
        }
    }
}

// ---------------- stage 4: gather ----------------
__global__ void k_gather(const float* __restrict__ u_base, const float* __restrict__ pos,
                         const float* __restrict__ vel){
    int idx = blockIdx.x*blockDim.x+threadIdx.x;
    if (idx >= NB*NS) return;
    int b = idx/NS, s = idx%NS;
    int n = g_topidx[idx];
    float p0=pos[(b*NN+n)*3+0], p1=pos[(b*NN+n)*3+1], p2=pos[(b*NN+n)*3+2];
    g_possel[idx*3+0]=p0; g_possel[idx*3+1]=p1; g_possel[idx*3+2]=p2;
    g_masksel[idx] = g_soft[b*NN+n];
    float vf = g_varpp[b*NN+n];
    float vl0=vel[((b*NT+NT-1)*NN+n)*NC+0];
    float vl1=vel[((b*NT+NT-1)*NN+n)*NC+1];
    float vl2=vel[((b*NT+NT-1)*NN+n)*NC+2];
    for (int k=0;k<NK;k++){
        float* row = &g_x0[((b*NK+k)*NS+s)*10];
        row[0]=u_base[((b*NK+k)*NN+n)*NC+0];
        row[1]=u_base[((b*NK+k)*NN+n)*NC+1];
        row[2]=u_base[((b*NK+k)*NN+n)*NC+2];
        row[3]=vl0; row[4]=vl1; row[5]=vl2;
        row[6]=p0;  row[7]=p1;  row[8]=p2;
        row[9]=vf;
    }
}

// ---------------- stage 5: warp-per-node KNN (+indeg count) ----------------
__global__ __launch_bounds__(128) void k_knn(){
    __shared__ float sd[4][32][16];
    __shared__ int   si[4][32][16];
    int w = threadIdx.x>>5, lane = threadIdx.x&31;
    int node = blockIdx.x*4 + w;
    if (node >= NB*NS) return;
    int b = node/NS, s = node%NS;
    const float* __restrict__ P = &g_possel[b*NS*3];
    float px=P[s*3], py=P[s*3+1], pz=P[s*3+2];
    float bd[16]; int bi[16];
    #pragma unroll
    for (int i=0;i<16;i++){ bd[i]=3.4e38f; bi[i]=0x7fffffff; }
    for (int t=lane; t<NS; t+=32){
        if (t==s) continue;
        float dx=P[t*3]-px, dy=P[t*3+1]-py, dz=P[t*3+2]-pz;
        float d2 = dx*dx+dy*dy+dz*dz;
        if (d2 > bd[15] || (d2==bd[15] && t>bi[15])) continue;
        float cd=d2; int ci=t;
        #pragma unroll
        for (int p=0;p<16;p++){
            bool better = (cd<bd[p]) || (cd==bd[p] && ci<bi[p]);
            if (better){
                float tf=bd[p]; bd[p]=cd; cd=tf;
                int   ti=bi[p]; bi[p]=ci; ci=ti;
            }
        }
    }
    #pragma unroll
    for (int i=0;i<16;i++){ sd[w][lane][i]=bd[i]; si[w][lane][i]=bi[i]; }
    __syncwarp();
    int ptr=0;
    int myres = 0;
    for (int r=0;r<16;r++){
        unsigned long long key =
            ((unsigned long long)__float_as_uint(sd[w][lane][ptr])<<32) |
            (unsigned int)si[w][lane][ptr];
        unsigned long long mn = key;
        #pragma unroll
        for (int o=16;o;o>>=1){
            unsigned long long other = __shfl_xor_sync(0xffffffffu, mn, o);
            if (other < mn) mn = other;
        }
        if (mn == key) ptr++;
        if (lane == r) myres = (int)(unsigned int)(mn & 0xffffffffull);
    }
    if (lane < NKN){
        int i = myres;
        int e = s*NKN + lane;
        g_ei[b*NE+e] = i;
        atomicAdd(&g_indeg[b*NS+i], 1);
        float rx=P[i*3]-px, ry=P[i*3+1]-py, rz=P[i*3+2]-pz;
        float dist = sqrtf(rx*rx+ry*ry+rz*rz);
        float* ea = &g_ea[(b*NE+e)*4];
        ea[0]=rx; ea[1]=ry; ea[2]=rz; ea[3]=dist;
    }
}

// ---------------- stage 6: reverse-CSR ----------------
__global__ void k_zero(){
    int i = blockIdx.x*blockDim.x+threadIdx.x;
    if (i < NB*NS) g_indeg[i]=0;
}
__global__ __launch_bounds__(1024) void k_scan(){
    __shared__ int sc[2048];
    int b = blockIdx.x, tid = threadIdx.x;
    for (int i=tid;i<2048;i+=1024) sc[i] = (i<NS)? g_indeg[b*NS+i] : 0;
    __syncthreads();
    for (int off=1; off<2048; off<<=1){
        int i0=tid, i1=tid+1024;
        int v0 = sc[i0] + (i0>=off ? sc[i0-off] : 0);
        int v1 = sc[i1] + (i1>=off ? sc[i1-off] : 0);
        __syncthreads();
        sc[i0]=v0; sc[i1]=v1;
        __syncthreads();
    }
    for (int s=tid;s<NS;s+=1024){
        int st = s ? sc[s-1] : 0;
        g_revstart[b*(NS+1)+s] = st;
        g_cursor[b*NS+s] = st;
    }
    if (tid==0) g_revstart[b*(NS+1)+NS] = sc[NS-1];
}
__global__ void k_fill(){
    int idx = blockIdx.x*blockDim.x+threadIdx.x;
    if (idx >= NB*NE) return;
    int b = idx/NE, e = idx%NE;
    int i = g_ei[idx];
    int p = atomicAdd(&g_cursor[b*NS+i], 1);
    g_revlist[b*NE+p] = e;
}

// ---------------- tf32 tensor-core GEMM: 64x64 tile, K=192 fixed ----------------
__global__ __launch_bounds__(128) void k_gemmtc(
    const float* __restrict__ X, int Mrows,
    const float* __restrict__ Wf,
    const float* __restrict__ bias, int do_gelu,
    float* __restrict__ Out, int ldo)
{
    __shared__ unsigned int As[64][20];
    int tid = threadIdx.x;
    int lane = tid & 31, wid = tid >> 5;
    int wm = (wid & 1) * 32, wn = (wid >> 1) * 32;
    int bm = blockIdx.y * 64, bn = blockIdx.x * 64;
    float acc[2][4][4] = {};
    int am = tid >> 1, akq = (tid & 1) * 8;
    int grow = bm + am;
    bool rowok = grow < Mrows;
    const float* Xr = X + (size_t)grow * 192;
    const float2* Bf = (const float2*)Wf;
    int tn0 = (bn + wn) >> 3;

    for (int kt = 0; kt < 12; kt++){
        int k0 = kt * 16;
        {
            float4 v0 = {0,0,0,0}, v1 = {0,0,0,0};
            if (rowok){
                v0 = *reinterpret_cast<const float4*>(Xr + k0 + akq);
                v1 = *reinterpret_cast<const float4*>(Xr + k0 + akq + 4);
            }
            As[am][akq+0]=to_tf32(v0.x); As[am][akq+1]=to_tf32(v0.y);
            As[am][akq+2]=to_tf32(v0.z); As[am][akq+3]=to_tf32(v0.w);
            As[am][akq+4]=to_tf32(v1.x); As[am][akq+5]=to_tf32(v1.y);
            As[am][akq+6]=to_tf32(v1.z); As[am][akq+7]=to_tf32(v1.w);
        }
        __syncthreads();
        #pragma unroll
        for (int h=0; h<2; h++){
            int kk = h*8;
            int tk8 = kt*2 + h;
            unsigned int bf0[4], bf1[4];
            #pragma unroll
            for (int nt=0; nt<4; nt++){
                float2 bv = Bf[(((size_t)(tn0+nt))*24 + tk8)*32 + lane];
                bf0[nt] = __float_as_uint(bv.x);
                bf1[nt] = __float_as_uint(bv.y);
            }
            unsigned int af[2][4];
            #pragma unroll
            for (int mt=0; mt<2; mt++){
                int r0 = wm + mt*16 + (lane>>2);
                int c0 = kk + (lane&3);
                af[mt][0] = As[r0][c0];
                af[mt][1] = As[r0+8][c0];
                af[mt][2] = As[r0][c0+4];
                af[mt][3] = As[r0+8][c0+4];
            }
            #pragma unroll
            for (int nt=0; nt<4; nt++){
                #pragma unroll
                for (int mt=0; mt<2; mt++){
                    asm("mma.sync.aligned.m16n8k8.row.col.f32.tf32.tf32.f32 "
                        "{%0,%1,%2,%3}, {%4,%5,%6,%7}, {%8,%9}, {%0,%1,%2,%3};"
                        : "+f"(acc[mt][nt][0]), "+f"(acc[mt][nt][1]),
                          "+f"(acc[mt][nt][2]), "+f"(acc[mt][nt][3])
                        : "r"(af[mt][0]), "r"(af[mt][1]), "r"(af[mt][2]), "r"(af[mt][3]),
                          "r"(bf0[nt]), "r"(bf1[nt]));
                }
            }
        }
        __syncthreads();
    }
    #pragma unroll
    for (int mt=0; mt<2; mt++){
        int r0 = bm + wm + mt*16 + (lane>>2);
        #pragma unroll
        for (int nt=0; nt<4; nt++){
            int c0 = bn + wn + nt*8 + 2*(lane&3);
            float b0v = bias ? bias[c0]   : 0.0f;
            float b1v = bias ? bias[c0+1] : 0.0f;
            if (r0 < Mrows){
                float o0 = acc[mt][nt][0] + b0v;
                float o1 = acc[mt][nt][1] + b1v;
                if (do_gelu){ o0 = gelu_f(o0); o1 = gelu_f(o1); }
                Out[(size_t)r0*ldo + c0]   = o0;
                Out[(size_t)r0*ldo + c0+1] = o1;
            }
            if (r0+8 < Mrows){
                float o2 = acc[mt][nt][2] + b0v;
                float o3 = acc[mt][nt][3] + b1v;
                if (do_gelu){ o2 = gelu_f(o2); o3 = gelu_f(o3); }
                Out[(size_t)(r0+8)*ldo + c0]   = o2;
                Out[(size_t)(r0+8)*ldo + c0+1] = o3;
            }
        }
    }
}

// ---------------- tf32 tensor-core GEMM2 + indeg*b2 + LayerNorm + residual ----------------
__global__ __launch_bounds__(256) void k_gemmlntc(
    const float* __restrict__ X,      // G, NM x 192
    const float* __restrict__ W2f,    // w2 fragment tf32
    const float* __restrict__ b2,
    const float* __restrict__ gamma, const float* __restrict__ beta,
    int add_resid, float* __restrict__ outp)
{
    __shared__ unsigned int As[32*196];
    int tid = threadIdx.x;
    int lane = tid & 31, w = tid >> 5;
    int bm = blockIdx.x*32;
    #pragma unroll
    for (int j=0;j<6;j++){
        int idx4 = tid + j*256;
        int row = idx4/48, c4 = (idx4%48)*4;
        int grow = bm+row;
        float4 v = {0.f,0.f,0.f,0.f};
        if (grow < NM) v = *reinterpret_cast<const float4*>(X + (size_t)grow*192 + c4);
        uint4 t;
        t.x=to_tf32(v.x); t.y=to_tf32(v.y); t.z=to_tf32(v.z); t.w=to_tf32(v.w);
        *reinterpret_cast<uint4*>(&As[row*196 + c4]) = t;
    }
    __syncthreads();
    int wm = (w>>2)*16;
    int tn0 = (w&3)*6;
    const float2* Bf = (const float2*)W2f;
    float acc[6][4] = {};
    #pragma unroll 4
    for (int tk8=0; tk8<24; tk8++){
        int c0 = tk8*8 + (lane&3);
        int r0 = wm + (lane>>2);
        unsigned int a0 = As[r0*196 + c0];
        unsigned int a1 = As[(r0+8)*196 + c0];
        unsigned int a2 = As[r0*196 + c0+4];
        unsigned int a3 = As[(r0+8)*196 + c0+4];
        #pragma unroll
        for (int nt=0; nt<6; nt++){
            float2 bv = Bf[(((size_t)(tn0+nt))*24 + tk8)*32 + lane];
            asm("mma.sync.aligned.m16n8k8.row.col.f32.tf32.tf32.f32 "
                "{%0,%1,%2,%3}, {%4,%5,%6,%7}, {%8,%9}, {%0,%1,%2,%3};"
                : "+f"(acc[nt][0]), "+f"(acc[nt][1]), "+f"(acc[nt][2]), "+f"(acc[nt][3])
                : "r"(a0), "r"(a1), "r"(a2), "r"(a3),
                  "r"(__float_as_uint(bv.x)), "r"(__float_as_uint(bv.y)));
        }
    }
    __syncthreads();
    float* Cs = (float*)As;
    {
        int r = wm + (lane>>2);
        #pragma unroll
        for (int nt=0; nt<6; nt++){
            int c = (tn0+nt)*8 + 2*(lane&3);
            Cs[r*196+c]       = acc[nt][0];
            Cs[r*196+c+1]     = acc[nt][1];
            Cs[(r+8)*196+c]   = acc[nt][2];
            Cs[(r+8)*196+c+1] = acc[nt][3];
        }
    }
    __syncthreads();
    #pragma unroll
    for (int i=0;i<4;i++){
        int row = w*4+i;
        int r = bm + row;
        if (r >= NM) continue;
        int s = r % NS;
        int b = r / (NK*NS);
        float deg = (float)g_indeg[b*NS+s];
        float xr[6];
        float sum=0;
        #pragma unroll
        for (int c=0;c<6;c++){
            int col = lane + 32*c;
            float v = Cs[row*196 + col] + deg*b2[col];
            xr[c]=v; sum+=v;
        }
        #pragma unroll
        for (int o=16;o;o>>=1) sum += __shfl_xor_sync(0xffffffffu,sum,o);
        float mu = sum*(1.0f/NH);
        float vs=0;
        #pragma unroll
        for (int c=0;c<6;c++){ float d=xr[c]-mu; vs+=d*d; }
        #pragma unroll
        for (int o=16;o;o>>=1) vs += __shfl_xor_sync(0xffffffffu,vs,o);
        float inv = 1.0f/sqrtf(vs*(1.0f/NH)+1e-5f);
        #pragma unroll
        for (int c=0;c<6;c++){
            int col = lane + 32*c;
            float y = (xr[c]-mu)*inv*gamma[col] + beta[col];
            if (add_resid) y += g_h[(size_t)r*NH+col];
            outp[(size_t)r*NH+col] = y;
        }
    }
}

// ---------------- SIMT fp32 GEMM (layer0 only, K=10) ----------------
__global__ __launch_bounds__(128) void k_gemm3(
    const float* __restrict__ X, int lda, int Mrows, int Kd,
    const float* __restrict__ W, int ldw,
    const float* __restrict__ bias, int do_gelu,
    float* __restrict__ Out, int ldo)
{
    __shared__ float As[8][64];
    __shared__ float Bs[8][64];
    int tid = threadIdx.x;
    int tx = tid & 7, ty = tid >> 3;
    int bm = blockIdx.y * 64, bn = blockIdx.x * 64;
    u64t acc2[2][8] = {};
    int lr = tid >> 1;
    int lk = (tid & 1) * 4;
    int kb = tid >> 4, nb = (tid & 15) * 4;
    int ktiles = (Kd+7)>>3;
    for (int kt=0;kt<ktiles;kt++){
        int k0 = kt*8;
        {
            int grow = bm + lr;
            const float* Xr = X + (size_t)grow*lda;
            #pragma unroll
            for (int q=0;q<4;q++){
                int gk = k0+lk+q;
                As[lk+q][lr] = (grow<Mrows && gk<Kd)? Xr[gk] : 0.0f;
            }
        }
        {
            int gk = k0+kb;
            float4 v = {0.f,0.f,0.f,0.f};
            if (gk < Kd) v = *reinterpret_cast<const float4*>(W + (size_t)gk*ldw + bn + nb);
            *reinterpret_cast<float4*>(&Bs[kb][nb]) = v;
        }
        __syncthreads();
        #pragma unroll
        for (int kk=0;kk<8;kk++){
            float4 a = *reinterpret_cast<const float4*>(&As[kk][ty*4]);
            float4 b0 = *reinterpret_cast<const float4*>(&Bs[kk][tx*4]);
            float4 b1 = *reinterpret_cast<const float4*>(&Bs[kk][32+tx*4]);
            u64t ap[2] = { pk2(a.x,a.y), pk2(a.z,a.w) };
            float br[8]={b0.x,b0.y,b0.z,b0.w,b1.x,b1.y,b1.z,b1.w};
            #pragma unroll
            for (int j=0;j<8;j++){
                u64t bb = pk2(br[j],br[j]);
                acc2[0][j] = fma2(ap[0], bb, acc2[0][j]);
                acc2[1][j] = fma2(ap[1], bb, acc2[1][j]);
            }
        }
        __syncthreads();
    }
    #pragma unroll
    for (int i=0;i<2;i++){
        int rbase = bm + ty*4 + i*2;
        #pragma unroll
        for (int j=0;j<8;j++){
            int c = bn + ((j<4)? (tx*4+j) : (32+tx*4+(j-4)));
            float2 v = upk2(acc2[i][j]);
            float bv = bias ? bias[c] : 0.0f;
            if (rbase < Mrows){
                float o = v.x + bv;
                if (do_gelu) o = gelu_f(o);
                Out[(size_t)rbase*ldo + c] = o;
            }
            if (rbase+1 < Mrows){
                float o = v.y + bv;
                if (do_gelu) o = gelu_f(o);
                Out[(size_t)(rbase+1)*ldo + c] = o;
            }
        }
    }
}

// ---------------- per-layer edge kernel (LUT gelu, value-level software pipeline) ----------------
__global__ __launch_bounds__(256) void k_edge(const float* __restrict__ w1c, const float* __restrict__ b1){
    __shared__ float sW[4*NH];
    __shared__ float sb[NH];
    __shared__ float2 sL[1024];
    int tid = threadIdx.x;
    for (int i=tid;i<4*NH;i+=blockDim.x) sW[i]=w1c[i];
    for (int i=tid;i<NH;i+=blockDim.x)   sb[i]=b1[i];
    for (int i=tid;i<1024;i+=blockDim.x) sL[i]=g_glut[i];
    __syncthreads();
    int warp = (blockIdx.x*blockDim.x + tid) >> 5;
    int lane = tid & 31;
    int r = warp;
    int s = r % NS;
    int bk = r / NS;
    int b = bk / NK;
    float a[6], acc[6];
    #pragma unroll
    for (int c=0;c<6;c++){
        a[c] = g_AB[r*384 + lane + 32*c] + sb[lane + 32*c];
        acc[c]=0.0f;
    }
    int st = g_revstart[b*(NS+1)+s];
    int en = g_revstart[b*(NS+1)+s+1];
    // prime pipeline: load first edge's values
    float4 ea_c = make_float4(0.f,0.f,0.f,0.f);
    float bm_c[6] = {0,0,0,0,0,0};
    if (st < en){
        int e0 = g_revlist[b*NE + st];
        ea_c = *reinterpret_cast<const float4*>(&g_ea[(b*NE + e0)*4]);
        const float* __restrict__ bmr = &g_AB[(bk*NS + (e0>>4))*384 + NH];
        #pragma unroll
        for (int c=0;c<6;c++) bm_c[c] = bmr[lane + 32*c];
    }
    for (int t=st;t<en;t++){
        // issue next edge's loads before computing current
        float4 ea_n = make_float4(0.f,0.f,0.f,0.f);
        float bm_n[6] = {0,0,0,0,0,0};
        if (t+1 < en){
            int e1 = g_revlist[b*NE + t + 1];
            ea_n = *reinterpret_cast<const float4*>(&g_ea[(b*NE + e1)*4]);
            const float* __restrict__ bmr = &g_AB[(bk*NS + (e1>>4))*384 + NH];
            #pragma unroll
            for (int c=0;c<6;c++) bm_n[c] = bmr[lane + 32*c];
        }
        #pragma unroll
        for (int c=0;c<6;c++){
            int col = lane + 32*c;
            float pre = a[c] + bm_c[c]
                      + ea_c.x*sW[col] + ea_c.y*sW[NH+col] + ea_c.z*sW[2*NH+col] + ea_c.w*sW[3*NH+col];
            float u = (pre + 6.0f) * (1024.0f/12.0f);
            u = fminf(fmaxf(u, 0.0f), 1023.999f);
            int ii = (int)u;
            float fr = u - (float)ii;
            float2 lv = sL[ii];
            acc[c] = fmaf(pre, fmaf(fr, lv.y, lv.x), acc[c]);
        }
        ea_c = ea_n;
        #pragma unroll
        for (int c=0;c<6;c++) bm_c[c] = bm_n[c];
    }
    #pragma unroll
    for (int c=0;c<6;c++) g_G[r*NH + lane + 32*c] = acc[c];
}

// ---------------- standalone LN (head) ----------------
__global__ __launch_bounds__(256) void k_ln(const float* __restrict__ in,
                     const float* __restrict__ gamma, const float* __restrict__ beta,
                     float* __restrict__ outp){
    int tid = threadIdx.x;
    int warp = (blockIdx.x*blockDim.x + tid) >> 5;
    int lane = tid & 31;
    int r = warp;
    float x[6];
    float sum=0;
    #pragma unroll
    for (int c=0;c<6;c++){
        int col = lane + 32*c;
        float v = in[r*NH+col];
        x[c]=v; sum+=v;
    }
    #pragma unroll
    for (int o=16;o;o>>=1) sum += __shfl_xor_sync(0xffffffffu,sum,o);
    float mu = sum*(1.0f/NH);
    float vs=0;
    #pragma unroll
    for (int c=0;c<6;c++){ float d=x[c]-mu; vs+=d*d; }
    #pragma unroll
    for (int o=16;o;o>>=1) vs += __shfl_xor_sync(0xffffffffu,vs,o);
    float inv = 1.0f/sqrtf(vs*(1.0f/NH)+1e-5f);
    #pragma unroll
    for (int c=0;c<6;c++){
        int col = lane + 32*c;
        outp[r*NH+col] = (x[c]-mu)*inv*gamma[col] + beta[col];
    }
}

// ---------------- head projection H->3 + mask ----------------
__global__ __launch_bounds__(256) void k_headout(const float* __restrict__ w2, const float* __restrict__ b2){
    int tid = threadIdx.x;
    int warp = (blockIdx.x*blockDim.x + tid) >> 5;
    int lane = tid & 31;
    int r = warp;
    int s = r % NS;
    int b = r / (NK*NS);
    float z6[6];
    #pragma unroll
    for (int c=0;c<6;c++) z6[c] = g_z[r*NH + lane + 32*c];
    float d[3];
    #pragma unroll
    for (int cc=0;cc<3;cc++){
        float p=0;
        #pragma unroll
        for (int c=0;c<6;c++){ int col = lane + 32*c; p += z6[c]*w2[col*3+cc]; }
        #pragma unroll
        for (int o=16;o;o>>=1) p += __shfl_xor_sync(0xffffffffu,p,o);
        d[cc]=p;
    }
    if (lane==0){
        float ms = g_masksel[b*NS+s];
        #pragma unroll
        for (int cc=0;cc<3;cc++) g_delta[r*3+cc] = (d[cc]+b2[cc])*ms;
    }
}

// ---------------- output ----------------
__global__ void k_outbase(const float* __restrict__ u, const float* __restrict__ am,
                          float* __restrict__ out){
    int idx = blockIdx.x*blockDim.x+threadIdx.x;
    if (idx >= NB*NK*NN*NC) return;
    int n = (idx/NC) % NN;
    int b = idx / (NC*NN*NK);
    out[idx] = u[idx]*(1.0f-am[b*NN+n]);
}
__global__ void k_scatter(const float* __restrict__ u, const float* __restrict__ am,
                          float* __restrict__ out){
    int idx = blockIdx.x*blockDim.x+threadIdx.x;
    if (idx >= NB*NK*NS*NC) return;
    int c = idx % NC;
    int s = (idx/NC) % NS;
    int k = (idx/(NC*NS)) % NK;
    int b = idx / (NC*NS*NK);
    int n = g_topidx[b*NS+s];
    float f = 1.0f - am[b*NN+n];
    int oi = ((b*NK+k)*NN+n)*NC + c;
    out[oi] = (u[oi] + g_delta[((b*NK+k)*NS+s)*3 + c]) * f;
}

// ---------------- launch ----------------
extern "C" void kernel_launch(void* const* d_in, const int* in_sizes, int n_in,
                              void* d_out, int out_size){
    const float* u_base   = (const float*)d_in[0];
    const float* pos      = (const float*)d_in[1];
    const float* vel      = (const float*)d_in[2];
    const float* am       = (const float*)d_in[3];
    const float* c0_w1    = (const float*)d_in[4];
    const float* c0_b1    = (const float*)d_in[5];
    const float* c0_w2    = (const float*)d_in[6];
    const float* c0_b2    = (const float*)d_in[7];
    const float* c0_g     = (const float*)d_in[8];
    const float* c0_be    = (const float*)d_in[9];
    const float* cs_w1    = (const float*)d_in[10];
    const float* cs_b1    = (const float*)d_in[11];
    const float* cs_w2    = (const float*)d_in[12];
    const float* cs_b2    = (const float*)d_in[13];
    const float* cs_g     = (const float*)d_in[14];
    const float* cs_be    = (const float*)d_in[15];
    const float* head_g   = (const float*)d_in[16];
    const float* head_be  = (const float*)d_in[17];
    const float* head_w1  = (const float*)d_in[18];
    const float* head_b1  = (const float*)d_in[19];
    const float* head_w2  = (const float*)d_in[20];
    const float* head_b2  = (const float*)d_in[21];
    float* out = (float*)d_out;

    float *x0p, *hp, *ABp, *Gp, *tp, *zp, *wc0p, *wcfp, *whfp, *w2fp;
    cudaGetSymbolAddress((void**)&x0p,  g_x0);
    cudaGetSymbolAddress((void**)&hp,   g_h);
    cudaGetSymbolAddress((void**)&ABp,  g_AB);
    cudaGetSymbolAddress((void**)&Gp,   g_G);
    cudaGetSymbolAddress((void**)&tp,   g_t);
    cudaGetSymbolAddress((void**)&zp,   g_z);
    cudaGetSymbolAddress((void**)&wc0p, g_Wc0);
    cudaGetSymbolAddress((void**)&wcfp, g_Wcf);
    cudaGetSymbolAddress((void**)&whfp, g_Whf);
    cudaGetSymbolAddress((void**)&w2fp, g_W2f);

    const int PREP_TOT = 10*384 + 9*192*384 + 192*192 + 10*192*192 + 1024;
    k_prep<<<(PREP_TOT+255)/256,256>>>(c0_w1, cs_w1, head_w1, c0_w2, cs_w2);
    k_varpp<<<(NB*NN+255)/256,256>>>(vel);
    k_stats<<<NB,1024>>>(am);
    k_select<<<NB,1024>>>();
    k_zero<<<(NB*NS+255)/256,256>>>();
    k_gather<<<(NB*NS+255)/256,256>>>(u_base,pos,vel);
    k_knn<<<(NB*NS+3)/4,128>>>();
    k_scan<<<NB,1024>>>();
    k_fill<<<(NB*NE+255)/256,256>>>();

    dim3 grid_ab(6,(NM+63)/64);        // 6 x 103
    dim3 grid_hd(3,(NM+63)/64);
    const int LN_BLOCKS = (NM+31)/32;  // 205
    const int EDGE_BLOCKS = NM/8;      // 819

    for (int l=0;l<10;l++){
        const float *w1raw, *w1c, *b1, *b2, *gm, *bt;
        int resid;
        if (l==0){
            w1raw=c0_w1; w1c=w1raw+2*10*NH; b1=c0_b1;
            b2=c0_b2; gm=c0_g; bt=c0_be; resid=0;
            k_gemm3<<<grid_ab,128>>>(x0p,10,NM,10,wc0p,384,nullptr,0,ABp,384);
        } else {
            int li=l-1;
            w1raw=cs_w1+(size_t)li*388*NH; w1c=w1raw+2*NH*NH; b1=cs_b1+li*NH;
            b2=cs_b2+li*NH;
            gm=cs_g+li*NH; bt=cs_be+li*NH; resid=1;
            k_gemmtc<<<grid_ab,128>>>(hp,NM,wcfp+(size_t)li*192*384,nullptr,0,ABp,384);
        }
        // pull edges, gelu (LUT), sum
        k_edge<<<EDGE_BLOCKS,256>>>(w1c,b1);
        // h = LN(G @ w2 + deg*b2) (+ residual) — tf32 tensor cores
        k_gemmlntc<<<LN_BLOCKS,256>>>(Gp, w2fp+(size_t)l*192*192, b2, gm, bt, resid, hp);
    }

    // head
    k_ln<<<EDGE_BLOCKS,256>>>(hp,head_g,head_be,tp);
    k_gemmtc<<<grid_hd,128>>>(tp,NM,whfp,head_b1,1,zp,NH);
    k_headout<<<EDGE_BLOCKS,256>>>(head_w2,head_b2);

    // output
    k_outbase<<<(NB*NK*NN*NC+255)/256,256>>>(u_base,am,out);
    k_scatter<<<(NB*NK*NS*NC+255)/256,256>>>(u_base,am,out);
}